// round 12
// baseline (speedup 1.0000x reference)
#include <cuda_runtime.h>
#include <cuda_bf16.h>
#include <stdint.h>
#include <math.h>

#define S_LEN   2048
#define D_MODEL 1024
#define NHEADS  16
#define DKH     64
#define HALF_WIN 128
#define BQ      64
#define BATCH   2
#define MROWS   (BATCH * S_LEN)   // 4096
#define K3      (3 * D_MODEL)     // 3072
#define NQKV    3072

// ---------------- scratch (static device globals; no allocation) -----------
__device__ __nv_bfloat16 g_qh  [MROWS * NQKV];       // qkv hi (bf16)
__device__ __nv_bfloat16 g_ql  [MROWS * NQKV];       // qkv lo (bf16)
__device__ __nv_bfloat16 g_xa  [MROWS * K3];         // x split [hi|lo|hi]
__device__ __nv_bfloat16 g_aoa [MROWS * K3];         // attn-out split [hi|lo|hi]
__device__ __nv_bfloat16 g_wqkv[NQKV * K3];          // [Wq;Wk;Wv] split [hi|hi|lo]
__device__ __nv_bfloat16 g_wo  [D_MODEL * K3];       // Wo split

// ---------------- fp32 -> bf16x3 split conversion ---------------------------
__device__ __forceinline__ void split_row(
    const float* __restrict__ in, __nv_bfloat16* __restrict__ out,
    int r, int c, int modeB)
{
    float4 v = *(const float4*)(in + (size_t)r * D_MODEL + c);
    float f[4] = {v.x, v.y, v.z, v.w};
    __nv_bfloat16 hi[4], lo[4];
    #pragma unroll
    for (int j = 0; j < 4; j++) {
        hi[j] = __float2bfloat16(f[j]);
        lo[j] = __float2bfloat16(f[j] - __bfloat162float(hi[j]));
    }
    __nv_bfloat162 hp0 = __halves2bfloat162(hi[0], hi[1]);
    __nv_bfloat162 hp1 = __halves2bfloat162(hi[2], hi[3]);
    __nv_bfloat162 lp0 = __halves2bfloat162(lo[0], lo[1]);
    __nv_bfloat162 lp1 = __halves2bfloat162(lo[2], lo[3]);
    __nv_bfloat162* o0 = (__nv_bfloat162*)(out + (size_t)r * K3 + c);
    __nv_bfloat162* o1 = (__nv_bfloat162*)(out + (size_t)r * K3 + D_MODEL + c);
    __nv_bfloat162* o2 = (__nv_bfloat162*)(out + (size_t)r * K3 + 2 * D_MODEL + c);
    o0[0] = hp0; o0[1] = hp1;
    if (modeB) { o1[0] = hp0; o1[1] = hp1; o2[0] = lp0; o2[1] = lp1; }
    else       { o1[0] = lp0; o1[1] = lp1; o2[0] = hp0; o2[1] = hp1; }
}

__global__ __launch_bounds__(256) void conv_split(
    const float* __restrict__ in, __nv_bfloat16* __restrict__ out, int modeB)
{
    split_row(in, out, blockIdx.x, threadIdx.x * 4, modeB);
}

__global__ __launch_bounds__(256) void conv_split_w(
    const float* __restrict__ Wq, const float* __restrict__ Wk,
    const float* __restrict__ Wv, const float* __restrict__ Wo,
    __nv_bfloat16* __restrict__ wqkv, __nv_bfloat16* __restrict__ wo)
{
    int w = blockIdx.y;
    const float* src = (w == 0) ? Wq : (w == 1) ? Wk : (w == 2) ? Wv : Wo;
    __nv_bfloat16* dst = (w == 3) ? wo : wqkv + (size_t)w * D_MODEL * K3;
    split_row(src, dst, blockIdx.x, threadIdx.x * 4, 1);
}

// ---------------- common PTX helpers ----------------------------------------
__device__ __forceinline__ uint32_t s2u(const void* p) {
    uint32_t a;
    asm("{ .reg .u64 t; cvta.to.shared.u64 t, %1; cvt.u32.u64 %0, t; }"
        : "=r"(a) : "l"(p));
    return a;
}
__device__ __forceinline__ void cp16(uint32_t dst, const void* src) {
    asm volatile("cp.async.cg.shared.global [%0], [%1], 16;" :: "r"(dst), "l"(src));
}
__device__ __forceinline__ void ldmx4(uint32_t& r0, uint32_t& r1, uint32_t& r2,
                                      uint32_t& r3, uint32_t addr) {
    asm volatile("ldmatrix.sync.aligned.m8n8.x4.shared.b16 {%0,%1,%2,%3}, [%4];"
                 : "=r"(r0), "=r"(r1), "=r"(r2), "=r"(r3) : "r"(addr));
}
__device__ __forceinline__ void ldmx4t(uint32_t& r0, uint32_t& r1, uint32_t& r2,
                                       uint32_t& r3, uint32_t addr) {
    asm volatile("ldmatrix.sync.aligned.m8n8.x4.trans.shared.b16 {%0,%1,%2,%3}, [%4];"
                 : "=r"(r0), "=r"(r1), "=r"(r2), "=r"(r3) : "r"(addr));
}
__device__ __forceinline__ void hmma(float* c, const uint32_t* a,
                                     uint32_t b0, uint32_t b1) {
    asm volatile(
        "mma.sync.aligned.m16n8k16.row.col.f32.bf16.bf16.f32 "
        "{%0,%1,%2,%3}, {%4,%5,%6,%7}, {%8,%9}, {%0,%1,%2,%3};"
        : "+f"(c[0]), "+f"(c[1]), "+f"(c[2]), "+f"(c[3])
        : "r"(a[0]), "r"(a[1]), "r"(a[2]), "r"(a[3]), "r"(b0), "r"(b1));
}
__device__ __forceinline__ uint32_t pkbf(float x, float y) {
    __nv_bfloat162 r = __halves2bfloat162(__float2bfloat16(x), __float2bfloat16(y));
    return *(uint32_t*)&r;
}

// ---------------- mma.sync bf16 GEMM: Y[M,N] = A[M,K3] @ B[N,K3]^T ----------
// CTA tile 128x256, 8 warps of 64x64, 1 CTA/SM.
// SPLIT=false: fp32 output; SPLIT=true: bf16 hi/lo split pair output.
#define GBM 128
#define GBN 256
#define GBK 64
#define PADK 72
#define STG 3
#define ASTG_B (GBM * PADK * 2)                    // 18432
#define BSTG_B (GBN * PADK * 2)                    // 36864
#define SMEM_GEMM (STG * (ASTG_B + BSTG_B))        // 165888 B

template <bool SPLIT>
__global__ __launch_bounds__(256, 1) void gemm_mma(
    const __nv_bfloat16* __restrict__ A,
    const __nv_bfloat16* __restrict__ B,
    float* __restrict__ Yf,
    __nv_bfloat16* __restrict__ Yh, __nv_bfloat16* __restrict__ Yl, int N)
{
    extern __shared__ __nv_bfloat16 smem_g[];

    int tid = threadIdx.x;
    int wid = tid >> 5, lane = tid & 31;
    int wm = wid & 1, wn = wid >> 1;            // 2 x 4 warps of 64x64
    int bm = blockIdx.y * GBM, bn = blockIdx.x * GBN;
    int g = lane >> 2, tig = lane & 3;

    int lrow = tid >> 3;                        // 0..31
    int lch  = tid & 7;                         // 0..7

    uint32_t as_base = s2u(smem_g);
    uint32_t bs_base = as_base + STG * ASTG_B;

    uint32_t a_ld = as_base +
        ((uint32_t)(wm * 64 + (lane & 15)) * PADK + ((lane >> 4) * 8)) * 2;
    uint32_t b_ld = bs_base +
        ((uint32_t)(wn * 64 + (lane >> 4) * 8 + (lane & 7)) * PADK +
         (((lane >> 3) & 1) * 8)) * 2;

    const int NIT = K3 / GBK;                   // 48

#define LOAD_STAGE(s, k0)                                                       \
    do {                                                                        \
        _Pragma("unroll")                                                       \
        for (int i = 0; i < 4; i++) {                                           \
            int row = lrow + i * 32;                                            \
            cp16(as_base + (uint32_t)(s) * ASTG_B + (row * PADK + lch * 8) * 2, \
                 A + (size_t)(bm + row) * K3 + (k0) + lch * 8);                 \
        }                                                                       \
        _Pragma("unroll")                                                       \
        for (int i = 0; i < 8; i++) {                                           \
            int row = lrow + i * 32;                                            \
            cp16(bs_base + (uint32_t)(s) * BSTG_B + (row * PADK + lch * 8) * 2, \
                 B + (size_t)(bn + row) * K3 + (k0) + lch * 8);                 \
        }                                                                       \
    } while (0)

    LOAD_STAGE(0, 0);
    asm volatile("cp.async.commit_group;");
    LOAD_STAGE(1, GBK);
    asm volatile("cp.async.commit_group;");

    float acc[4][8][4];
    #pragma unroll
    for (int i = 0; i < 4; i++)
        #pragma unroll
        for (int j = 0; j < 8; j++)
            #pragma unroll
            for (int t = 0; t < 4; t++) acc[i][j][t] = 0.f;

    int s = 0;
    for (int it = 0; it < NIT; it++) {
        asm volatile("cp.async.wait_group 1;");
        __syncthreads();

        uint32_t a_s = a_ld + s * ASTG_B;
        uint32_t b_s = b_ld + s * BSTG_B;

        #pragma unroll
        for (int kk = 0; kk < GBK; kk += 16) {
            uint32_t af[4][4], bf[8][2];
            #pragma unroll
            for (int i = 0; i < 4; i++)
                ldmx4(af[i][0], af[i][1], af[i][2], af[i][3],
                      a_s + (uint32_t)(i * 16 * PADK + kk) * 2);
            #pragma unroll
            for (int np = 0; np < 4; np++)
                ldmx4(bf[2*np][0], bf[2*np][1], bf[2*np+1][0], bf[2*np+1][1],
                      b_s + (uint32_t)(np * 16 * PADK + kk) * 2);
            #pragma unroll
            for (int i = 0; i < 4; i++)
                #pragma unroll
                for (int j = 0; j < 8; j++)
                    hmma(acc[i][j], af[i], bf[j][0], bf[j][1]);
        }

        int s2 = s + 2; if (s2 >= STG) s2 -= STG;
        if (it + 2 < NIT) LOAD_STAGE(s2, (it + 2) * GBK);
        asm volatile("cp.async.commit_group;");
        s = s + 1; if (s >= STG) s = 0;
    }

    if (SPLIT) {
        #pragma unroll
        for (int i = 0; i < 4; i++) {
            int r = bm + wm * 64 + i * 16 + g;
            #pragma unroll
            for (int j = 0; j < 8; j++) {
                int c = bn + wn * 64 + j * 8 + 2 * tig;
                #pragma unroll
                for (int half = 0; half < 2; half++) {
                    float v0 = acc[i][j][2*half], v1 = acc[i][j][2*half+1];
                    __nv_bfloat16 h0 = __float2bfloat16(v0);
                    __nv_bfloat16 h1 = __float2bfloat16(v1);
                    __nv_bfloat16 l0 = __float2bfloat16(v0 - __bfloat162float(h0));
                    __nv_bfloat16 l1 = __float2bfloat16(v1 - __bfloat162float(h1));
                    size_t idx = (size_t)(r + 8*half) * N + c;
                    *(__nv_bfloat162*)&Yh[idx] = __halves2bfloat162(h0, h1);
                    *(__nv_bfloat162*)&Yl[idx] = __halves2bfloat162(l0, l1);
                }
            }
        }
    } else {
        #pragma unroll
        for (int i = 0; i < 4; i++) {
            int r = bm + wm * 64 + i * 16 + g;
            #pragma unroll
            for (int j = 0; j < 8; j++) {
                int c = bn + wn * 64 + j * 8 + 2 * tig;
                *(float2*)&Yf[(size_t)r * N + c]       = make_float2(acc[i][j][0], acc[i][j][1]);
                *(float2*)&Yf[(size_t)(r + 8) * N + c] = make_float2(acc[i][j][2], acc[i][j][3]);
            }
        }
    }
#undef LOAD_STAGE
}

// ---------------- tensor-core windowed ALiBi flash attention (R10 proven) ---
#define TPAD 72
#define TILE_BYTES (64 * TPAD * 2)     // 9216
#define QH_OFF 0
#define QL_OFF (1 * TILE_BYTES)
#define KH_OFF (2 * TILE_BYTES)
#define KL_OFF (3 * TILE_BYTES)
#define VH_OFF (4 * TILE_BYTES)
#define VL_OFF (5 * TILE_BYTES)
#define SMEM_ATTN (6 * TILE_BYTES)     // 55296

__device__ __forceinline__ void ldtile(
    char* smp, int off, const __nv_bfloat16* __restrict__ gsrc, int tid)
{
    #pragma unroll
    for (int i = 0; i < 4; i++) {
        int idx = tid + i * 128;
        int row = idx >> 3, ch = idx & 7;
        uint4 val = *(const uint4*)(gsrc + (size_t)row * NQKV + ch * 8);
        *(uint4*)(smp + off + (row * TPAD + ch * 8) * 2) = val;
    }
}

__global__ __launch_bounds__(128) void attn_tc(
    const __nv_bfloat16* __restrict__ qkvh,
    const __nv_bfloat16* __restrict__ qkvl,
    const float* __restrict__ slopes,
    __nv_bfloat16* __restrict__ oa)
{
    extern __shared__ char smc[];
    uint32_t sb = s2u(smc);

    int qt = blockIdx.x, h = blockIdx.y, b = blockIdx.z;
    int q0 = qt * BQ;
    int tid = threadIdx.x, wid = tid >> 5, lane = tid & 31;
    int g = lane >> 2, t = lane & 3;
    int m0 = wid * 16;
    float slope = slopes[h];

    size_t qbase = ((size_t)b * S_LEN + q0) * NQKV + h * DKH;
    ldtile(smc, QH_OFF, qkvh + qbase, tid);
    ldtile(smc, QL_OFF, qkvl + qbase, tid);
    __syncthreads();

    uint32_t arow = ((uint32_t)(m0 + (lane & 15)) * TPAD + ((lane >> 4) * 8)) * 2;
    uint32_t qh4[4][4], ql4[4][4];
    #pragma unroll
    for (int s = 0; s < 4; s++) {
        ldmx4(qh4[s][0], qh4[s][1], qh4[s][2], qh4[s][3],
              sb + QH_OFF + arow + s * 32);
        ldmx4(ql4[s][0], ql4[s][1], ql4[s][2], ql4[s][3],
              sb + QL_OFF + arow + s * 32);
    }

    float oc[8][4];
    #pragma unroll
    for (int nt = 0; nt < 8; nt++)
        #pragma unroll
        for (int e = 0; e < 4; e++) oc[nt][e] = 0.f;
    float m2[2] = {-INFINITY, -INFINITY};
    float l2[2] = {0.f, 0.f};

    uint32_t brow = (((uint32_t)((lane >> 4) * 8 + (lane & 7))) * TPAD +
                     ((lane >> 3) & 1) * 8) * 2;
    uint32_t vrow = (((uint32_t)(((lane >> 3) & 1) * 8 + (lane & 7))) * TPAD +
                     ((lane >> 4) * 8)) * 2;

    int kstart = q0 - HALF_WIN; if (kstart < 0) kstart = 0;
    int kend   = q0 + BQ + HALF_WIN; if (kend > S_LEN) kend = S_LEN;

    for (int kc = kstart; kc < kend; kc += 64) {
        __syncthreads();
        size_t kb = ((size_t)b * S_LEN + kc) * NQKV + D_MODEL + h * DKH;
        size_t vb = ((size_t)b * S_LEN + kc) * NQKV + 2 * D_MODEL + h * DKH;
        ldtile(smc, KH_OFF, qkvh + kb, tid);
        ldtile(smc, KL_OFF, qkvl + kb, tid);
        ldtile(smc, VH_OFF, qkvh + vb, tid);
        ldtile(smc, VL_OFF, qkvl + vb, tid);
        __syncthreads();

        float sc[8][4];
        #pragma unroll
        for (int nt = 0; nt < 8; nt++)
            #pragma unroll
            for (int e = 0; e < 4; e++) sc[nt][e] = 0.f;

        #pragma unroll
        for (int s = 0; s < 4; s++) {
            uint32_t kbf[8][2];
            #pragma unroll
            for (int np = 0; np < 4; np++)
                ldmx4(kbf[2*np][0], kbf[2*np][1], kbf[2*np+1][0], kbf[2*np+1][1],
                      sb + KH_OFF + brow + (uint32_t)(np * 16 * TPAD) * 2 + s * 32);
            #pragma unroll
            for (int nt = 0; nt < 8; nt++) hmma(sc[nt], qh4[s], kbf[nt][0], kbf[nt][1]);
            #pragma unroll
            for (int nt = 0; nt < 8; nt++) hmma(sc[nt], ql4[s], kbf[nt][0], kbf[nt][1]);
            #pragma unroll
            for (int np = 0; np < 4; np++)
                ldmx4(kbf[2*np][0], kbf[2*np][1], kbf[2*np+1][0], kbf[2*np+1][1],
                      sb + KL_OFF + brow + (uint32_t)(np * 16 * TPAD) * 2 + s * 32);
            #pragma unroll
            for (int nt = 0; nt < 8; nt++) hmma(sc[nt], qh4[s], kbf[nt][0], kbf[nt][1]);
        }

        #pragma unroll
        for (int nt = 0; nt < 8; nt++) {
            #pragma unroll
            for (int e = 0; e < 4; e++) {
                int row = q0 + m0 + g + (e >= 2 ? 8 : 0);
                int col = kc + nt * 8 + 2 * t + (e & 1);
                int d = row - col;
                float sv = sc[nt][e] * 0.125f + slope * (float)d;
                if (d > HALF_WIN || d < -HALF_WIN) sv = -INFINITY;
                sc[nt][e] = sv;
            }
        }

        #pragma unroll
        for (int half = 0; half < 2; half++) {
            float mx = -INFINITY;
            #pragma unroll
            for (int nt = 0; nt < 8; nt++)
                mx = fmaxf(mx, fmaxf(sc[nt][2*half], sc[nt][2*half+1]));
            mx = fmaxf(mx, __shfl_xor_sync(0xffffffffu, mx, 1));
            mx = fmaxf(mx, __shfl_xor_sync(0xffffffffu, mx, 2));
            float mnew = fmaxf(m2[half], mx);

            float alpha, lsum = 0.f;
            if (mnew == -INFINITY) {
                alpha = 1.f;
                #pragma unroll
                for (int nt = 0; nt < 8; nt++) {
                    sc[nt][2*half] = 0.f; sc[nt][2*half+1] = 0.f;
                }
            } else {
                alpha = __expf(m2[half] - mnew);
                #pragma unroll
                for (int nt = 0; nt < 8; nt++) {
                    float p0 = __expf(sc[nt][2*half]   - mnew);
                    float p1 = __expf(sc[nt][2*half+1] - mnew);
                    sc[nt][2*half] = p0; sc[nt][2*half+1] = p1;
                    lsum += p0 + p1;
                }
            }
            lsum += __shfl_xor_sync(0xffffffffu, lsum, 1);
            lsum += __shfl_xor_sync(0xffffffffu, lsum, 2);
            l2[half] = l2[half] * alpha + lsum;
            m2[half] = mnew;
            #pragma unroll
            for (int nt = 0; nt < 8; nt++) {
                oc[nt][2*half]   *= alpha;
                oc[nt][2*half+1] *= alpha;
            }
        }

        #pragma unroll
        for (int kk = 0; kk < 4; kk++) {
            uint32_t ah[4], al[4];
            {
                float p00 = sc[2*kk][0],   p01 = sc[2*kk][1];
                float p10 = sc[2*kk][2],   p11 = sc[2*kk][3];
                float p20 = sc[2*kk+1][0], p21 = sc[2*kk+1][1];
                float p30 = sc[2*kk+1][2], p31 = sc[2*kk+1][3];
                ah[0] = pkbf(p00, p01); ah[1] = pkbf(p10, p11);
                ah[2] = pkbf(p20, p21); ah[3] = pkbf(p30, p31);
                float r00 = p00 - __bfloat162float(__float2bfloat16(p00));
                float r01 = p01 - __bfloat162float(__float2bfloat16(p01));
                float r10 = p10 - __bfloat162float(__float2bfloat16(p10));
                float r11 = p11 - __bfloat162float(__float2bfloat16(p11));
                float r20 = p20 - __bfloat162float(__float2bfloat16(p20));
                float r21 = p21 - __bfloat162float(__float2bfloat16(p21));
                float r30 = p30 - __bfloat162float(__float2bfloat16(p30));
                float r31 = p31 - __bfloat162float(__float2bfloat16(p31));
                al[0] = pkbf(r00, r01); al[1] = pkbf(r10, r11);
                al[2] = pkbf(r20, r21); al[3] = pkbf(r30, r31);
            }
            uint32_t vbf[8][2];
            #pragma unroll
            for (int np = 0; np < 4; np++)
                ldmx4t(vbf[2*np][0], vbf[2*np][1], vbf[2*np+1][0], vbf[2*np+1][1],
                       sb + VH_OFF + vrow + (uint32_t)(kk * 16 * TPAD + np * 16) * 2);
            #pragma unroll
            for (int nt = 0; nt < 8; nt++) hmma(oc[nt], ah, vbf[nt][0], vbf[nt][1]);
            #pragma unroll
            for (int nt = 0; nt < 8; nt++) hmma(oc[nt], al, vbf[nt][0], vbf[nt][1]);
            #pragma unroll
            for (int np = 0; np < 4; np++)
                ldmx4t(vbf[2*np][0], vbf[2*np][1], vbf[2*np+1][0], vbf[2*np+1][1],
                       sb + VL_OFF + vrow + (uint32_t)(kk * 16 * TPAD + np * 16) * 2);
            #pragma unroll
            for (int nt = 0; nt < 8; nt++) hmma(oc[nt], ah, vbf[nt][0], vbf[nt][1]);
        }
    }

    float inv0 = 1.f / l2[0], inv1 = 1.f / l2[1];
    int row0 = q0 + m0 + g;
    size_t r0b = ((size_t)b * S_LEN + row0) * K3 + h * DKH;
    size_t r1b = ((size_t)b * S_LEN + row0 + 8) * K3 + h * DKH;
    #pragma unroll
    for (int nt = 0; nt < 8; nt++) {
        int col = nt * 8 + 2 * t;
        #pragma unroll
        for (int half = 0; half < 2; half++) {
            float v0 = oc[nt][2*half]   * (half ? inv1 : inv0);
            float v1 = oc[nt][2*half+1] * (half ? inv1 : inv0);
            __nv_bfloat16 h0 = __float2bfloat16(v0);
            __nv_bfloat16 h1 = __float2bfloat16(v1);
            __nv_bfloat16 l0 = __float2bfloat16(v0 - __bfloat162float(h0));
            __nv_bfloat16 l1 = __float2bfloat16(v1 - __bfloat162float(h1));
            size_t base = (half ? r1b : r0b) + col;
            *(__nv_bfloat162*)&oa[base]               = __halves2bfloat162(h0, h1);
            *(__nv_bfloat162*)&oa[base + D_MODEL]     = __halves2bfloat162(l0, l1);
            *(__nv_bfloat162*)&oa[base + 2 * D_MODEL] = __halves2bfloat162(h0, h1);
        }
    }
}

// ---------------------------------------------------------------------------
extern "C" void kernel_launch(void* const* d_in, const int* in_sizes, int n_in,
                              void* d_out, int out_size)
{
    const float* x      = (const float*)d_in[0];
    const float* Wq     = (const float*)d_in[1];
    const float* Wk     = (const float*)d_in[2];
    const float* Wv     = (const float*)d_in[3];
    const float* Wo     = (const float*)d_in[4];
    const float* slopes = (const float*)d_in[5];
    float* out = (float*)d_out;

    __nv_bfloat16 *qh, *ql, *xa, *aoa, *wqkv, *wo;
    cudaGetSymbolAddress((void**)&qh,   g_qh);
    cudaGetSymbolAddress((void**)&ql,   g_ql);
    cudaGetSymbolAddress((void**)&xa,   g_xa);
    cudaGetSymbolAddress((void**)&aoa,  g_aoa);
    cudaGetSymbolAddress((void**)&wqkv, g_wqkv);
    cudaGetSymbolAddress((void**)&wo,   g_wo);

    cudaFuncSetAttribute(gemm_mma<true>, cudaFuncAttributeMaxDynamicSharedMemorySize,
                         SMEM_GEMM);
    cudaFuncSetAttribute(gemm_mma<true>, cudaFuncAttributePreferredSharedMemoryCarveout,
                         100);
    cudaFuncSetAttribute(gemm_mma<false>, cudaFuncAttributeMaxDynamicSharedMemorySize,
                         SMEM_GEMM);
    cudaFuncSetAttribute(gemm_mma<false>, cudaFuncAttributePreferredSharedMemoryCarveout,
                         100);
    cudaFuncSetAttribute(attn_tc, cudaFuncAttributeMaxDynamicSharedMemorySize,
                         SMEM_ATTN);
    cudaFuncSetAttribute(attn_tc, cudaFuncAttributePreferredSharedMemoryCarveout,
                         100);

    conv_split<<<MROWS, 256>>>(x, xa, 0);
    conv_split_w<<<dim3(D_MODEL, 4), 256>>>(Wq, Wk, Wv, Wo, wqkv, wo);

    // QKV projection -> bf16 hi/lo pair arrays (split epilogue instantiation)
    gemm_mma<true><<<dim3(NQKV / GBN, MROWS / GBM), 256, SMEM_GEMM>>>(
        xa, wqkv, nullptr, qh, ql, NQKV);

    // tensor-core attention -> split aoa directly
    attn_tc<<<dim3(S_LEN / BQ, NHEADS, BATCH), 128, SMEM_ATTN>>>(
        qh, ql, slopes, aoa);

    // output projection -> fp32 result (lean fp32 instantiation)
    gemm_mma<false><<<dim3(D_MODEL / GBN, MROWS / GBM), 256, SMEM_GEMM>>>(
        aoa, wo, out, nullptr, nullptr, D_MODEL);
}

// round 13
// speedup vs baseline: 1.3611x; 1.3611x over previous
#include <cuda_runtime.h>
#include <cuda_fp16.h>
#include <stdint.h>
#include <math.h>

#define S_LEN   2048
#define D_MODEL 1024
#define NHEADS  16
#define DKH     64
#define HALF_WIN 128
#define BQ      64
#define BATCH   2
#define MROWS   (BATCH * S_LEN)   // 4096
#define K2      (2 * D_MODEL)     // 2048
#define NQKV    3072

// ---------------- scratch (static device globals; no allocation) -----------
__device__ __half g_qh  [MROWS * NQKV];              // qkv hi (fp16)
__device__ __half g_ql  [MROWS * NQKV];              // qkv lo (fp16)
__device__ __half g_xa  [MROWS * K2];                // x split [hi|lo]
__device__ __half g_aoa [MROWS * K2];                // attn-out split [hi|lo]
__device__ __half g_wqkv[NQKV * K2];                 // [Wq;Wk;Wv] split [hi|hi]
__device__ __half g_wo  [D_MODEL * K2];              // Wo split [hi|hi]

// ---------------- fp32 -> fp16x2 split conversion ----------------------------
// modeB=0 (activations): blocks [hi | lo];  modeB=1 (weights): [hi | hi]
__device__ __forceinline__ void split_row(
    const float* __restrict__ in, __half* __restrict__ out,
    int r, int c, int modeB)
{
    float4 v = *(const float4*)(in + (size_t)r * D_MODEL + c);
    float f[4] = {v.x, v.y, v.z, v.w};
    __half hi[4], lo[4];
    #pragma unroll
    for (int j = 0; j < 4; j++) {
        hi[j] = __float2half(f[j]);
        lo[j] = __float2half(f[j] - __half2float(hi[j]));
    }
    __half2 hp0 = __halves2half2(hi[0], hi[1]);
    __half2 hp1 = __halves2half2(hi[2], hi[3]);
    __half2 lp0 = __halves2half2(lo[0], lo[1]);
    __half2 lp1 = __halves2half2(lo[2], lo[3]);
    __half2* o0 = (__half2*)(out + (size_t)r * K2 + c);
    __half2* o1 = (__half2*)(out + (size_t)r * K2 + D_MODEL + c);
    o0[0] = hp0; o0[1] = hp1;
    if (modeB) { o1[0] = hp0; o1[1] = hp1; }
    else       { o1[0] = lp0; o1[1] = lp1; }
}

__global__ __launch_bounds__(256) void conv_split(
    const float* __restrict__ in, __half* __restrict__ out, int modeB)
{
    split_row(in, out, blockIdx.x, threadIdx.x * 4, modeB);
}

__global__ __launch_bounds__(256) void conv_split_w(
    const float* __restrict__ Wq, const float* __restrict__ Wk,
    const float* __restrict__ Wv, const float* __restrict__ Wo,
    __half* __restrict__ wqkv, __half* __restrict__ wo)
{
    int w = blockIdx.y;
    const float* src = (w == 0) ? Wq : (w == 1) ? Wk : (w == 2) ? Wv : Wo;
    __half* dst = (w == 3) ? wo : wqkv + (size_t)w * D_MODEL * K2;
    split_row(src, dst, blockIdx.x, threadIdx.x * 4, 1);
}

// ---------------- common PTX helpers ----------------------------------------
__device__ __forceinline__ uint32_t s2u(const void* p) {
    uint32_t a;
    asm("{ .reg .u64 t; cvta.to.shared.u64 t, %1; cvt.u32.u64 %0, t; }"
        : "=r"(a) : "l"(p));
    return a;
}
__device__ __forceinline__ void cp16(uint32_t dst, const void* src) {
    asm volatile("cp.async.cg.shared.global [%0], [%1], 16;" :: "r"(dst), "l"(src));
}
__device__ __forceinline__ void ldmx4(uint32_t& r0, uint32_t& r1, uint32_t& r2,
                                      uint32_t& r3, uint32_t addr) {
    asm volatile("ldmatrix.sync.aligned.m8n8.x4.shared.b16 {%0,%1,%2,%3}, [%4];"
                 : "=r"(r0), "=r"(r1), "=r"(r2), "=r"(r3) : "r"(addr));
}
__device__ __forceinline__ void ldmx4t(uint32_t& r0, uint32_t& r1, uint32_t& r2,
                                       uint32_t& r3, uint32_t addr) {
    asm volatile("ldmatrix.sync.aligned.m8n8.x4.trans.shared.b16 {%0,%1,%2,%3}, [%4];"
                 : "=r"(r0), "=r"(r1), "=r"(r2), "=r"(r3) : "r"(addr));
}
__device__ __forceinline__ void hmma(float* c, const uint32_t* a,
                                     uint32_t b0, uint32_t b1) {
    asm volatile(
        "mma.sync.aligned.m16n8k16.row.col.f32.f16.f16.f32 "
        "{%0,%1,%2,%3}, {%4,%5,%6,%7}, {%8,%9}, {%0,%1,%2,%3};"
        : "+f"(c[0]), "+f"(c[1]), "+f"(c[2]), "+f"(c[3])
        : "r"(a[0]), "r"(a[1]), "r"(a[2]), "r"(a[3]), "r"(b0), "r"(b1));
}
__device__ __forceinline__ uint32_t pkh(float x, float y) {
    __half2 r = __halves2half2(__float2half(x), __float2half(y));
    return *(uint32_t*)&r;
}

// ---------------- mma.sync fp16 GEMM: Y[M,N] = A[M,K2] @ B[N,K2]^T ----------
// R11-proven tile: 128x128 CTA, 8 warps of 64x32, 2 CTA/SM, STG=3, GBK=64.
// SPLIT=false: fp32 output; SPLIT=true: fp16 hi/lo split pair output.
#define GBM 128
#define GBN 128
#define GBK 64
#define PADK 72
#define STG 3
#define SMEM_GEMM (STG * (GBM + GBN) * PADK * 2)   // 110592 B

template <bool SPLIT>
__global__ __launch_bounds__(256, 2) void gemm_mma(
    const __half* __restrict__ A,
    const __half* __restrict__ B,
    float* __restrict__ Yf,
    __half* __restrict__ Yh, __half* __restrict__ Yl, int N)
{
    extern __shared__ __half smem_g[];

    int tid = threadIdx.x;
    int wid = tid >> 5, lane = tid & 31;
    int wm = wid & 1, wn = wid >> 1;
    int bm = blockIdx.y * GBM, bn = blockIdx.x * GBN;
    int g = lane >> 2, tig = lane & 3;

    int lrow = tid >> 3;
    int lch  = tid & 7;

    uint32_t as_base = s2u(smem_g);
    uint32_t bs_base = as_base + STG * GBM * PADK * 2;

    uint32_t a_ld = as_base +
        ((uint32_t)(wm * 64 + (lane & 15)) * PADK + ((lane >> 4) * 8)) * 2;
    uint32_t b_ld = bs_base +
        ((uint32_t)(wn * 32 + (lane >> 4) * 8 + (lane & 7)) * PADK +
         (((lane >> 3) & 1) * 8)) * 2;

    const int NIT = K2 / GBK;                   // 32
    const uint32_t ASTG = GBM * PADK * 2;
    const uint32_t BSTG = GBN * PADK * 2;

#define LOAD_STAGE(s, k0)                                                     \
    do {                                                                      \
        _Pragma("unroll")                                                     \
        for (int i = 0; i < 4; i++) {                                         \
            int row = lrow + i * 32;                                          \
            cp16(as_base + (uint32_t)(s) * ASTG + (row * PADK + lch * 8) * 2, \
                 A + (size_t)(bm + row) * K2 + (k0) + lch * 8);               \
            cp16(bs_base + (uint32_t)(s) * BSTG + (row * PADK + lch * 8) * 2, \
                 B + (size_t)(bn + row) * K2 + (k0) + lch * 8);               \
        }                                                                     \
    } while (0)

    LOAD_STAGE(0, 0);
    asm volatile("cp.async.commit_group;");
    LOAD_STAGE(1, GBK);
    asm volatile("cp.async.commit_group;");

    float acc[4][4][4];
    #pragma unroll
    for (int i = 0; i < 4; i++)
        #pragma unroll
        for (int j = 0; j < 4; j++)
            #pragma unroll
            for (int t = 0; t < 4; t++) acc[i][j][t] = 0.f;

    int s = 0;
    for (int it = 0; it < NIT; it++) {
        asm volatile("cp.async.wait_group 1;");
        __syncthreads();

        uint32_t a_s = a_ld + s * ASTG;
        uint32_t b_s = b_ld + s * BSTG;

        #pragma unroll
        for (int kk = 0; kk < GBK; kk += 16) {
            uint32_t af[4][4], bf[4][2];
            #pragma unroll
            for (int i = 0; i < 4; i++)
                ldmx4(af[i][0], af[i][1], af[i][2], af[i][3],
                      a_s + (uint32_t)(i * 16 * PADK + kk) * 2);
            #pragma unroll
            for (int jp = 0; jp < 2; jp++)
                ldmx4(bf[2*jp][0], bf[2*jp][1], bf[2*jp+1][0], bf[2*jp+1][1],
                      b_s + (uint32_t)(jp * 16 * PADK + kk) * 2);
            #pragma unroll
            for (int i = 0; i < 4; i++)
                #pragma unroll
                for (int j = 0; j < 4; j++)
                    hmma(acc[i][j], af[i], bf[j][0], bf[j][1]);
        }

        int s2 = s + 2; if (s2 >= STG) s2 -= STG;
        if (it + 2 < NIT) LOAD_STAGE(s2, (it + 2) * GBK);
        asm volatile("cp.async.commit_group;");
        s = s + 1; if (s >= STG) s = 0;
    }

    if (SPLIT) {
        #pragma unroll
        for (int i = 0; i < 4; i++) {
            int r = bm + wm * 64 + i * 16 + g;
            #pragma unroll
            for (int j = 0; j < 4; j++) {
                int c = bn + wn * 32 + j * 8 + 2 * tig;
                #pragma unroll
                for (int half = 0; half < 2; half++) {
                    float v0 = acc[i][j][2*half], v1 = acc[i][j][2*half+1];
                    __half h0 = __float2half(v0);
                    __half h1 = __float2half(v1);
                    __half l0 = __float2half(v0 - __half2float(h0));
                    __half l1 = __float2half(v1 - __half2float(h1));
                    size_t idx = (size_t)(r + 8*half) * N + c;
                    *(__half2*)&Yh[idx] = __halves2half2(h0, h1);
                    *(__half2*)&Yl[idx] = __halves2half2(l0, l1);
                }
            }
        }
    } else {
        #pragma unroll
        for (int i = 0; i < 4; i++) {
            int r = bm + wm * 64 + i * 16 + g;
            #pragma unroll
            for (int j = 0; j < 4; j++) {
                int c = bn + wn * 32 + j * 8 + 2 * tig;
                *(float2*)&Yf[(size_t)r * N + c]       = make_float2(acc[i][j][0], acc[i][j][1]);
                *(float2*)&Yf[(size_t)(r + 8) * N + c] = make_float2(acc[i][j][2], acc[i][j][3]);
            }
        }
    }
#undef LOAD_STAGE
}

// ---------------- tensor-core windowed ALiBi flash attention ----------------
// fp16 pairs; 3-term QK and PV (dropped terms ~2^-22). Structure = R10/R11.
#define TPAD 72
#define TILE_BYTES (64 * TPAD * 2)     // 9216
#define QH_OFF 0
#define QL_OFF (1 * TILE_BYTES)
#define KH_OFF (2 * TILE_BYTES)
#define KL_OFF (3 * TILE_BYTES)
#define VH_OFF (4 * TILE_BYTES)
#define VL_OFF (5 * TILE_BYTES)
#define SMEM_ATTN (6 * TILE_BYTES)     // 55296

__device__ __forceinline__ void ldtile(
    char* smp, int off, const __half* __restrict__ gsrc, int tid)
{
    #pragma unroll
    for (int i = 0; i < 4; i++) {
        int idx = tid + i * 128;
        int row = idx >> 3, ch = idx & 7;
        uint4 val = *(const uint4*)(gsrc + (size_t)row * NQKV + ch * 8);
        *(uint4*)(smp + off + (row * TPAD + ch * 8) * 2) = val;
    }
}

__global__ __launch_bounds__(128) void attn_tc(
    const __half* __restrict__ qkvh,
    const __half* __restrict__ qkvl,
    const float* __restrict__ slopes,
    __half* __restrict__ oa)
{
    extern __shared__ char smc[];
    uint32_t sb = s2u(smc);

    int qt = blockIdx.x, h = blockIdx.y, b = blockIdx.z;
    int q0 = qt * BQ;
    int tid = threadIdx.x, wid = tid >> 5, lane = tid & 31;
    int g = lane >> 2, t = lane & 3;
    int m0 = wid * 16;
    float slope = slopes[h];

    size_t qbase = ((size_t)b * S_LEN + q0) * NQKV + h * DKH;
    ldtile(smc, QH_OFF, qkvh + qbase, tid);
    ldtile(smc, QL_OFF, qkvl + qbase, tid);
    __syncthreads();

    uint32_t arow = ((uint32_t)(m0 + (lane & 15)) * TPAD + ((lane >> 4) * 8)) * 2;
    uint32_t qh4[4][4], ql4[4][4];
    #pragma unroll
    for (int s = 0; s < 4; s++) {
        ldmx4(qh4[s][0], qh4[s][1], qh4[s][2], qh4[s][3],
              sb + QH_OFF + arow + s * 32);
        ldmx4(ql4[s][0], ql4[s][1], ql4[s][2], ql4[s][3],
              sb + QL_OFF + arow + s * 32);
    }

    float oc[8][4];
    #pragma unroll
    for (int nt = 0; nt < 8; nt++)
        #pragma unroll
        for (int e = 0; e < 4; e++) oc[nt][e] = 0.f;
    float m2[2] = {-INFINITY, -INFINITY};
    float l2[2] = {0.f, 0.f};

    uint32_t brow = (((uint32_t)((lane >> 4) * 8 + (lane & 7))) * TPAD +
                     ((lane >> 3) & 1) * 8) * 2;
    uint32_t vrow = (((uint32_t)(((lane >> 3) & 1) * 8 + (lane & 7))) * TPAD +
                     ((lane >> 4) * 8)) * 2;

    int kstart = q0 - HALF_WIN; if (kstart < 0) kstart = 0;
    int kend   = q0 + BQ + HALF_WIN; if (kend > S_LEN) kend = S_LEN;

    for (int kc = kstart; kc < kend; kc += 64) {
        __syncthreads();
        size_t kb = ((size_t)b * S_LEN + kc) * NQKV + D_MODEL + h * DKH;
        size_t vb = ((size_t)b * S_LEN + kc) * NQKV + 2 * D_MODEL + h * DKH;
        ldtile(smc, KH_OFF, qkvh + kb, tid);
        ldtile(smc, KL_OFF, qkvl + kb, tid);
        ldtile(smc, VH_OFF, qkvh + vb, tid);
        ldtile(smc, VL_OFF, qkvl + vb, tid);
        __syncthreads();

        float sc[8][4];
        #pragma unroll
        for (int nt = 0; nt < 8; nt++)
            #pragma unroll
            for (int e = 0; e < 4; e++) sc[nt][e] = 0.f;

        #pragma unroll
        for (int s = 0; s < 4; s++) {
            uint32_t kbf[8][2];
            #pragma unroll
            for (int np = 0; np < 4; np++)
                ldmx4(kbf[2*np][0], kbf[2*np][1], kbf[2*np+1][0], kbf[2*np+1][1],
                      sb + KH_OFF + brow + (uint32_t)(np * 16 * TPAD) * 2 + s * 32);
            #pragma unroll
            for (int nt = 0; nt < 8; nt++) hmma(sc[nt], qh4[s], kbf[nt][0], kbf[nt][1]);
            #pragma unroll
            for (int nt = 0; nt < 8; nt++) hmma(sc[nt], ql4[s], kbf[nt][0], kbf[nt][1]);
            #pragma unroll
            for (int np = 0; np < 4; np++)
                ldmx4(kbf[2*np][0], kbf[2*np][1], kbf[2*np+1][0], kbf[2*np+1][1],
                      sb + KL_OFF + brow + (uint32_t)(np * 16 * TPAD) * 2 + s * 32);
            #pragma unroll
            for (int nt = 0; nt < 8; nt++) hmma(sc[nt], qh4[s], kbf[nt][0], kbf[nt][1]);
        }

        #pragma unroll
        for (int nt = 0; nt < 8; nt++) {
            #pragma unroll
            for (int e = 0; e < 4; e++) {
                int row = q0 + m0 + g + (e >= 2 ? 8 : 0);
                int col = kc + nt * 8 + 2 * t + (e & 1);
                int d = row - col;
                float sv = sc[nt][e] * 0.125f + slope * (float)d;
                if (d > HALF_WIN || d < -HALF_WIN) sv = -INFINITY;
                sc[nt][e] = sv;
            }
        }

        #pragma unroll
        for (int half = 0; half < 2; half++) {
            float mx = -INFINITY;
            #pragma unroll
            for (int nt = 0; nt < 8; nt++)
                mx = fmaxf(mx, fmaxf(sc[nt][2*half], sc[nt][2*half+1]));
            mx = fmaxf(mx, __shfl_xor_sync(0xffffffffu, mx, 1));
            mx = fmaxf(mx, __shfl_xor_sync(0xffffffffu, mx, 2));
            float mnew = fmaxf(m2[half], mx);

            float alpha, lsum = 0.f;
            if (mnew == -INFINITY) {
                alpha = 1.f;
                #pragma unroll
                for (int nt = 0; nt < 8; nt++) {
                    sc[nt][2*half] = 0.f; sc[nt][2*half+1] = 0.f;
                }
            } else {
                alpha = __expf(m2[half] - mnew);
                #pragma unroll
                for (int nt = 0; nt < 8; nt++) {
                    float p0 = __expf(sc[nt][2*half]   - mnew);
                    float p1 = __expf(sc[nt][2*half+1] - mnew);
                    sc[nt][2*half] = p0; sc[nt][2*half+1] = p1;
                    lsum += p0 + p1;
                }
            }
            lsum += __shfl_xor_sync(0xffffffffu, lsum, 1);
            lsum += __shfl_xor_sync(0xffffffffu, lsum, 2);
            l2[half] = l2[half] * alpha + lsum;
            m2[half] = mnew;
            #pragma unroll
            for (int nt = 0; nt < 8; nt++) {
                oc[nt][2*half]   *= alpha;
                oc[nt][2*half+1] *= alpha;
            }
        }

        #pragma unroll
        for (int kk = 0; kk < 4; kk++) {
            uint32_t ah[4], al[4];
            {
                float p00 = sc[2*kk][0],   p01 = sc[2*kk][1];
                float p10 = sc[2*kk][2],   p11 = sc[2*kk][3];
                float p20 = sc[2*kk+1][0], p21 = sc[2*kk+1][1];
                float p30 = sc[2*kk+1][2], p31 = sc[2*kk+1][3];
                ah[0] = pkh(p00, p01); ah[1] = pkh(p10, p11);
                ah[2] = pkh(p20, p21); ah[3] = pkh(p30, p31);
                float r00 = p00 - __half2float(__float2half(p00));
                float r01 = p01 - __half2float(__float2half(p01));
                float r10 = p10 - __half2float(__float2half(p10));
                float r11 = p11 - __half2float(__float2half(p11));
                float r20 = p20 - __half2float(__float2half(p20));
                float r21 = p21 - __half2float(__float2half(p21));
                float r30 = p30 - __half2float(__float2half(p30));
                float r31 = p31 - __half2float(__float2half(p31));
                al[0] = pkh(r00, r01); al[1] = pkh(r10, r11);
                al[2] = pkh(r20, r21); al[3] = pkh(r30, r31);
            }
            uint32_t vbf[8][2];
            #pragma unroll
            for (int np = 0; np < 4; np++)
                ldmx4t(vbf[2*np][0], vbf[2*np][1], vbf[2*np+1][0], vbf[2*np+1][1],
                       sb + VH_OFF + vrow + (uint32_t)(kk * 16 * TPAD + np * 16) * 2);
            #pragma unroll
            for (int nt = 0; nt < 8; nt++) hmma(oc[nt], ah, vbf[nt][0], vbf[nt][1]);
            #pragma unroll
            for (int nt = 0; nt < 8; nt++) hmma(oc[nt], al, vbf[nt][0], vbf[nt][1]);
            #pragma unroll
            for (int np = 0; np < 4; np++)
                ldmx4t(vbf[2*np][0], vbf[2*np][1], vbf[2*np+1][0], vbf[2*np+1][1],
                       sb + VL_OFF + vrow + (uint32_t)(kk * 16 * TPAD + np * 16) * 2);
            #pragma unroll
            for (int nt = 0; nt < 8; nt++) hmma(oc[nt], ah, vbf[nt][0], vbf[nt][1]);
        }
    }

    // epilogue: normalize + fp16 pair split write [hi | lo] into aoa (K2-wide)
    float inv0 = 1.f / l2[0], inv1 = 1.f / l2[1];
    int row0 = q0 + m0 + g;
    size_t r0b = ((size_t)b * S_LEN + row0) * K2 + h * DKH;
    size_t r1b = ((size_t)b * S_LEN + row0 + 8) * K2 + h * DKH;
    #pragma unroll
    for (int nt = 0; nt < 8; nt++) {
        int col = nt * 8 + 2 * t;
        #pragma unroll
        for (int half = 0; half < 2; half++) {
            float v0 = oc[nt][2*half]   * (half ? inv1 : inv0);
            float v1 = oc[nt][2*half+1] * (half ? inv1 : inv0);
            __half h0 = __float2half(v0);
            __half h1 = __float2half(v1);
            __half l0 = __float2half(v0 - __half2float(h0));
            __half l1 = __float2half(v1 - __half2float(h1));
            size_t base = (half ? r1b : r0b) + col;
            *(__half2*)&oa[base]           = __halves2half2(h0, h1);
            *(__half2*)&oa[base + D_MODEL] = __halves2half2(l0, l1);
        }
    }
}

// ---------------------------------------------------------------------------
extern "C" void kernel_launch(void* const* d_in, const int* in_sizes, int n_in,
                              void* d_out, int out_size)
{
    const float* x      = (const float*)d_in[0];
    const float* Wq     = (const float*)d_in[1];
    const float* Wk     = (const float*)d_in[2];
    const float* Wv     = (const float*)d_in[3];
    const float* Wo     = (const float*)d_in[4];
    const float* slopes = (const float*)d_in[5];
    float* out = (float*)d_out;

    __half *qh, *ql, *xa, *aoa, *wqkv, *wo;
    cudaGetSymbolAddress((void**)&qh,   g_qh);
    cudaGetSymbolAddress((void**)&ql,   g_ql);
    cudaGetSymbolAddress((void**)&xa,   g_xa);
    cudaGetSymbolAddress((void**)&aoa,  g_aoa);
    cudaGetSymbolAddress((void**)&wqkv, g_wqkv);
    cudaGetSymbolAddress((void**)&wo,   g_wo);

    cudaFuncSetAttribute(gemm_mma<true>, cudaFuncAttributeMaxDynamicSharedMemorySize,
                         SMEM_GEMM);
    cudaFuncSetAttribute(gemm_mma<true>, cudaFuncAttributePreferredSharedMemoryCarveout,
                         100);
    cudaFuncSetAttribute(gemm_mma<false>, cudaFuncAttributeMaxDynamicSharedMemorySize,
                         SMEM_GEMM);
    cudaFuncSetAttribute(gemm_mma<false>, cudaFuncAttributePreferredSharedMemoryCarveout,
                         100);
    cudaFuncSetAttribute(attn_tc, cudaFuncAttributeMaxDynamicSharedMemorySize,
                         SMEM_ATTN);
    cudaFuncSetAttribute(attn_tc, cudaFuncAttributePreferredSharedMemoryCarveout,
                         100);

    conv_split<<<MROWS, 256>>>(x, xa, 0);
    conv_split_w<<<dim3(D_MODEL, 4), 256>>>(Wq, Wk, Wv, Wo, wqkv, wo);

    // QKV projection -> fp16 hi/lo pair arrays (split epilogue)
    gemm_mma<true><<<dim3(NQKV / GBN, MROWS / GBM), 256, SMEM_GEMM>>>(
        xa, wqkv, nullptr, qh, ql, NQKV);

    // tensor-core attention -> split aoa directly
    attn_tc<<<dim3(S_LEN / BQ, NHEADS, BATCH), 128, SMEM_ATTN>>>(
        qh, ql, slopes, aoa);

    // output projection -> fp32 result
    gemm_mma<false><<<dim3(D_MODEL / GBN, MROWS / GBM), 256, SMEM_GEMM>>>(
        aoa, wo, out, nullptr, nullptr, D_MODEL);
}

// round 14
// speedup vs baseline: 1.7963x; 1.3197x over previous
#include <cuda_runtime.h>
#include <cuda_fp16.h>
#include <stdint.h>
#include <math.h>

#define S_LEN   2048
#define D_MODEL 1024
#define NHEADS  16
#define DKH     64
#define HALF_WIN 128
#define BQ      64
#define BATCH   2
#define MROWS   (BATCH * S_LEN)   // 4096
#define K2      (2 * D_MODEL)     // 2048
#define NQKV    3072

// ---------------- scratch (static device globals; no allocation) -----------
__device__ __half g_qh  [MROWS * NQKV];              // qkv hi (fp16)
__device__ __half g_ql  [MROWS * NQKV];              // qkv lo (fp16)
__device__ __half g_xa  [MROWS * D_MODEL];           // x plain fp16
__device__ __half g_aoa [MROWS * K2];                // attn-out split [hi|lo]
__device__ __half g_wqkv[NQKV * D_MODEL];            // [Wq;Wk;Wv] plain fp16
__device__ __half g_wo  [D_MODEL * K2];              // Wo split [hi|hi]

// ---------------- fp32 -> fp16 conversions -----------------------------------
__global__ __launch_bounds__(256) void conv_plain(
    const float* __restrict__ in, __half* __restrict__ out)
{
    int r = blockIdx.x;
    int c = threadIdx.x * 4;
    float4 v = *(const float4*)(in + (size_t)r * D_MODEL + c);
    __half2* o = (__half2*)(out + (size_t)r * D_MODEL + c);
    o[0] = __halves2half2(__float2half(v.x), __float2half(v.y));
    o[1] = __halves2half2(__float2half(v.z), __float2half(v.w));
}

// Wq/Wk/Wv -> plain fp16 (K=1024); Wo -> [hi|hi] split (K=2048)
__global__ __launch_bounds__(256) void conv_w(
    const float* __restrict__ Wq, const float* __restrict__ Wk,
    const float* __restrict__ Wv, const float* __restrict__ Wo,
    __half* __restrict__ wqkv, __half* __restrict__ wo)
{
    int w = blockIdx.y;
    int r = blockIdx.x;
    int c = threadIdx.x * 4;
    const float* src = (w == 0) ? Wq : (w == 1) ? Wk : (w == 2) ? Wv : Wo;
    float4 v = *(const float4*)(src + (size_t)r * D_MODEL + c);
    __half2 p0 = __halves2half2(__float2half(v.x), __float2half(v.y));
    __half2 p1 = __halves2half2(__float2half(v.z), __float2half(v.w));
    if (w < 3) {
        __half2* o = (__half2*)(wqkv + ((size_t)w * D_MODEL + r) * D_MODEL + c);
        o[0] = p0; o[1] = p1;
    } else {
        __half2* o0 = (__half2*)(wo + (size_t)r * K2 + c);
        __half2* o1 = (__half2*)(wo + (size_t)r * K2 + D_MODEL + c);
        o0[0] = p0; o0[1] = p1;
        o1[0] = p0; o1[1] = p1;
    }
}

// ---------------- common PTX helpers ----------------------------------------
__device__ __forceinline__ uint32_t s2u(const void* p) {
    uint32_t a;
    asm("{ .reg .u64 t; cvta.to.shared.u64 t, %1; cvt.u32.u64 %0, t; }"
        : "=r"(a) : "l"(p));
    return a;
}
__device__ __forceinline__ void cp16(uint32_t dst, const void* src) {
    asm volatile("cp.async.cg.shared.global [%0], [%1], 16;" :: "r"(dst), "l"(src));
}
__device__ __forceinline__ void ldmx4(uint32_t& r0, uint32_t& r1, uint32_t& r2,
                                      uint32_t& r3, uint32_t addr) {
    asm volatile("ldmatrix.sync.aligned.m8n8.x4.shared.b16 {%0,%1,%2,%3}, [%4];"
                 : "=r"(r0), "=r"(r1), "=r"(r2), "=r"(r3) : "r"(addr));
}
__device__ __forceinline__ void ldmx4t(uint32_t& r0, uint32_t& r1, uint32_t& r2,
                                       uint32_t& r3, uint32_t addr) {
    asm volatile("ldmatrix.sync.aligned.m8n8.x4.trans.shared.b16 {%0,%1,%2,%3}, [%4];"
                 : "=r"(r0), "=r"(r1), "=r"(r2), "=r"(r3) : "r"(addr));
}
__device__ __forceinline__ void hmma(float* c, const uint32_t* a,
                                     uint32_t b0, uint32_t b1) {
    asm volatile(
        "mma.sync.aligned.m16n8k16.row.col.f32.f16.f16.f32 "
        "{%0,%1,%2,%3}, {%4,%5,%6,%7}, {%8,%9}, {%0,%1,%2,%3};"
        : "+f"(c[0]), "+f"(c[1]), "+f"(c[2]), "+f"(c[3])
        : "r"(a[0]), "r"(a[1]), "r"(a[2]), "r"(a[3]), "r"(b0), "r"(b1));
}
__device__ __forceinline__ uint32_t pkh(float x, float y) {
    __half2 r = __halves2half2(__float2half(x), __float2half(y));
    return *(uint32_t*)&r;
}

// ---------------- mma.sync fp16 GEMM: Y[M,N] = A[M,KD] @ B[N,KD]^T ----------
// 128x128 CTA, 8 warps of 64x32, 2 CTA/SM, STG=3, GBK=64 (R11/R13 proven).
#define GBM 128
#define GBN 128
#define GBK 64
#define PADK 72
#define STG 3
#define SMEM_GEMM (STG * (GBM + GBN) * PADK * 2)   // 110592 B

template <bool SPLIT, int KD>
__global__ __launch_bounds__(256, 2) void gemm_mma(
    const __half* __restrict__ A,
    const __half* __restrict__ B,
    float* __restrict__ Yf,
    __half* __restrict__ Yh, __half* __restrict__ Yl, int N)
{
    extern __shared__ __half smem_g[];

    int tid = threadIdx.x;
    int wid = tid >> 5, lane = tid & 31;
    int wm = wid & 1, wn = wid >> 1;
    int bm = blockIdx.y * GBM, bn = blockIdx.x * GBN;
    int g = lane >> 2, tig = lane & 3;

    int lrow = tid >> 3;
    int lch  = tid & 7;

    uint32_t as_base = s2u(smem_g);
    uint32_t bs_base = as_base + STG * GBM * PADK * 2;

    uint32_t a_ld = as_base +
        ((uint32_t)(wm * 64 + (lane & 15)) * PADK + ((lane >> 4) * 8)) * 2;
    uint32_t b_ld = bs_base +
        ((uint32_t)(wn * 32 + (lane >> 4) * 8 + (lane & 7)) * PADK +
         (((lane >> 3) & 1) * 8)) * 2;

    const int NIT = KD / GBK;
    const uint32_t ASTG = GBM * PADK * 2;
    const uint32_t BSTG = GBN * PADK * 2;

#define LOAD_STAGE(s, k0)                                                     \
    do {                                                                      \
        _Pragma("unroll")                                                     \
        for (int i = 0; i < 4; i++) {                                         \
            int row = lrow + i * 32;                                          \
            cp16(as_base + (uint32_t)(s) * ASTG + (row * PADK + lch * 8) * 2, \
                 A + (size_t)(bm + row) * KD + (k0) + lch * 8);               \
            cp16(bs_base + (uint32_t)(s) * BSTG + (row * PADK + lch * 8) * 2, \
                 B + (size_t)(bn + row) * KD + (k0) + lch * 8);               \
        }                                                                     \
    } while (0)

    LOAD_STAGE(0, 0);
    asm volatile("cp.async.commit_group;");
    LOAD_STAGE(1, GBK);
    asm volatile("cp.async.commit_group;");

    float acc[4][4][4];
    #pragma unroll
    for (int i = 0; i < 4; i++)
        #pragma unroll
        for (int j = 0; j < 4; j++)
            #pragma unroll
            for (int t = 0; t < 4; t++) acc[i][j][t] = 0.f;

    int s = 0;
    for (int it = 0; it < NIT; it++) {
        asm volatile("cp.async.wait_group 1;");
        __syncthreads();

        uint32_t a_s = a_ld + s * ASTG;
        uint32_t b_s = b_ld + s * BSTG;

        #pragma unroll
        for (int kk = 0; kk < GBK; kk += 16) {
            uint32_t af[4][4], bf[4][2];
            #pragma unroll
            for (int i = 0; i < 4; i++)
                ldmx4(af[i][0], af[i][1], af[i][2], af[i][3],
                      a_s + (uint32_t)(i * 16 * PADK + kk) * 2);
            #pragma unroll
            for (int jp = 0; jp < 2; jp++)
                ldmx4(bf[2*jp][0], bf[2*jp][1], bf[2*jp+1][0], bf[2*jp+1][1],
                      b_s + (uint32_t)(jp * 16 * PADK + kk) * 2);
            #pragma unroll
            for (int i = 0; i < 4; i++)
                #pragma unroll
                for (int j = 0; j < 4; j++)
                    hmma(acc[i][j], af[i], bf[j][0], bf[j][1]);
        }

        int s2 = s + 2; if (s2 >= STG) s2 -= STG;
        if (it + 2 < NIT) LOAD_STAGE(s2, (it + 2) * GBK);
        asm volatile("cp.async.commit_group;");
        s = s + 1; if (s >= STG) s = 0;
    }

    if (SPLIT) {
        #pragma unroll
        for (int i = 0; i < 4; i++) {
            int r = bm + wm * 64 + i * 16 + g;
            #pragma unroll
            for (int j = 0; j < 4; j++) {
                int c = bn + wn * 32 + j * 8 + 2 * tig;
                #pragma unroll
                for (int half = 0; half < 2; half++) {
                    float v0 = acc[i][j][2*half], v1 = acc[i][j][2*half+1];
                    __half h0 = __float2half(v0);
                    __half h1 = __float2half(v1);
                    __half l0 = __float2half(v0 - __half2float(h0));
                    __half l1 = __float2half(v1 - __half2float(h1));
                    size_t idx = (size_t)(r + 8*half) * N + c;
                    *(__half2*)&Yh[idx] = __halves2half2(h0, h1);
                    *(__half2*)&Yl[idx] = __halves2half2(l0, l1);
                }
            }
        }
    } else {
        #pragma unroll
        for (int i = 0; i < 4; i++) {
            int r = bm + wm * 64 + i * 16 + g;
            #pragma unroll
            for (int j = 0; j < 4; j++) {
                int c = bn + wn * 32 + j * 8 + 2 * tig;
                *(float2*)&Yf[(size_t)r * N + c]       = make_float2(acc[i][j][0], acc[i][j][1]);
                *(float2*)&Yf[(size_t)(r + 8) * N + c] = make_float2(acc[i][j][2], acc[i][j][3]);
            }
        }
    }
#undef LOAD_STAGE
}

// ---------------- tensor-core windowed ALiBi flash attention (R13 proven) ---
#define TPAD 72
#define TILE_BYTES (64 * TPAD * 2)     // 9216
#define QH_OFF 0
#define QL_OFF (1 * TILE_BYTES)
#define KH_OFF (2 * TILE_BYTES)
#define KL_OFF (3 * TILE_BYTES)
#define VH_OFF (4 * TILE_BYTES)
#define VL_OFF (5 * TILE_BYTES)
#define SMEM_ATTN (6 * TILE_BYTES)     // 55296

__device__ __forceinline__ void ldtile(
    char* smp, int off, const __half* __restrict__ gsrc, int tid)
{
    #pragma unroll
    for (int i = 0; i < 4; i++) {
        int idx = tid + i * 128;
        int row = idx >> 3, ch = idx & 7;
        uint4 val = *(const uint4*)(gsrc + (size_t)row * NQKV + ch * 8);
        *(uint4*)(smp + off + (row * TPAD + ch * 8) * 2) = val;
    }
}

__global__ __launch_bounds__(128) void attn_tc(
    const __half* __restrict__ qkvh,
    const __half* __restrict__ qkvl,
    const float* __restrict__ slopes,
    __half* __restrict__ oa)
{
    extern __shared__ char smc[];
    uint32_t sb = s2u(smc);

    int qt = blockIdx.x, h = blockIdx.y, b = blockIdx.z;
    int q0 = qt * BQ;
    int tid = threadIdx.x, wid = tid >> 5, lane = tid & 31;
    int g = lane >> 2, t = lane & 3;
    int m0 = wid * 16;
    float slope = slopes[h];

    size_t qbase = ((size_t)b * S_LEN + q0) * NQKV + h * DKH;
    ldtile(smc, QH_OFF, qkvh + qbase, tid);
    ldtile(smc, QL_OFF, qkvl + qbase, tid);
    __syncthreads();

    uint32_t arow = ((uint32_t)(m0 + (lane & 15)) * TPAD + ((lane >> 4) * 8)) * 2;
    uint32_t qh4[4][4], ql4[4][4];
    #pragma unroll
    for (int s = 0; s < 4; s++) {
        ldmx4(qh4[s][0], qh4[s][1], qh4[s][2], qh4[s][3],
              sb + QH_OFF + arow + s * 32);
        ldmx4(ql4[s][0], ql4[s][1], ql4[s][2], ql4[s][3],
              sb + QL_OFF + arow + s * 32);
    }

    float oc[8][4];
    #pragma unroll
    for (int nt = 0; nt < 8; nt++)
        #pragma unroll
        for (int e = 0; e < 4; e++) oc[nt][e] = 0.f;
    float m2[2] = {-INFINITY, -INFINITY};
    float l2[2] = {0.f, 0.f};

    uint32_t brow = (((uint32_t)((lane >> 4) * 8 + (lane & 7))) * TPAD +
                     ((lane >> 3) & 1) * 8) * 2;
    uint32_t vrow = (((uint32_t)(((lane >> 3) & 1) * 8 + (lane & 7))) * TPAD +
                     ((lane >> 4) * 8)) * 2;

    int kstart = q0 - HALF_WIN; if (kstart < 0) kstart = 0;
    int kend   = q0 + BQ + HALF_WIN; if (kend > S_LEN) kend = S_LEN;

    for (int kc = kstart; kc < kend; kc += 64) {
        __syncthreads();
        size_t kb = ((size_t)b * S_LEN + kc) * NQKV + D_MODEL + h * DKH;
        size_t vb = ((size_t)b * S_LEN + kc) * NQKV + 2 * D_MODEL + h * DKH;
        ldtile(smc, KH_OFF, qkvh + kb, tid);
        ldtile(smc, KL_OFF, qkvl + kb, tid);
        ldtile(smc, VH_OFF, qkvh + vb, tid);
        ldtile(smc, VL_OFF, qkvl + vb, tid);
        __syncthreads();

        float sc[8][4];
        #pragma unroll
        for (int nt = 0; nt < 8; nt++)
            #pragma unroll
            for (int e = 0; e < 4; e++) sc[nt][e] = 0.f;

        #pragma unroll
        for (int s = 0; s < 4; s++) {
            uint32_t kbf[8][2];
            #pragma unroll
            for (int np = 0; np < 4; np++)
                ldmx4(kbf[2*np][0], kbf[2*np][1], kbf[2*np+1][0], kbf[2*np+1][1],
                      sb + KH_OFF + brow + (uint32_t)(np * 16 * TPAD) * 2 + s * 32);
            #pragma unroll
            for (int nt = 0; nt < 8; nt++) hmma(sc[nt], qh4[s], kbf[nt][0], kbf[nt][1]);
            #pragma unroll
            for (int nt = 0; nt < 8; nt++) hmma(sc[nt], ql4[s], kbf[nt][0], kbf[nt][1]);
            #pragma unroll
            for (int np = 0; np < 4; np++)
                ldmx4(kbf[2*np][0], kbf[2*np][1], kbf[2*np+1][0], kbf[2*np+1][1],
                      sb + KL_OFF + brow + (uint32_t)(np * 16 * TPAD) * 2 + s * 32);
            #pragma unroll
            for (int nt = 0; nt < 8; nt++) hmma(sc[nt], qh4[s], kbf[nt][0], kbf[nt][1]);
        }

        #pragma unroll
        for (int nt = 0; nt < 8; nt++) {
            #pragma unroll
            for (int e = 0; e < 4; e++) {
                int row = q0 + m0 + g + (e >= 2 ? 8 : 0);
                int col = kc + nt * 8 + 2 * t + (e & 1);
                int d = row - col;
                float sv = sc[nt][e] * 0.125f + slope * (float)d;
                if (d > HALF_WIN || d < -HALF_WIN) sv = -INFINITY;
                sc[nt][e] = sv;
            }
        }

        #pragma unroll
        for (int half = 0; half < 2; half++) {
            float mx = -INFINITY;
            #pragma unroll
            for (int nt = 0; nt < 8; nt++)
                mx = fmaxf(mx, fmaxf(sc[nt][2*half], sc[nt][2*half+1]));
            mx = fmaxf(mx, __shfl_xor_sync(0xffffffffu, mx, 1));
            mx = fmaxf(mx, __shfl_xor_sync(0xffffffffu, mx, 2));
            float mnew = fmaxf(m2[half], mx);

            float alpha, lsum = 0.f;
            if (mnew == -INFINITY) {
                alpha = 1.f;
                #pragma unroll
                for (int nt = 0; nt < 8; nt++) {
                    sc[nt][2*half] = 0.f; sc[nt][2*half+1] = 0.f;
                }
            } else {
                alpha = __expf(m2[half] - mnew);
                #pragma unroll
                for (int nt = 0; nt < 8; nt++) {
                    float p0 = __expf(sc[nt][2*half]   - mnew);
                    float p1 = __expf(sc[nt][2*half+1] - mnew);
                    sc[nt][2*half] = p0; sc[nt][2*half+1] = p1;
                    lsum += p0 + p1;
                }
            }
            lsum += __shfl_xor_sync(0xffffffffu, lsum, 1);
            lsum += __shfl_xor_sync(0xffffffffu, lsum, 2);
            l2[half] = l2[half] * alpha + lsum;
            m2[half] = mnew;
            #pragma unroll
            for (int nt = 0; nt < 8; nt++) {
                oc[nt][2*half]   *= alpha;
                oc[nt][2*half+1] *= alpha;
            }
        }

        #pragma unroll
        for (int kk = 0; kk < 4; kk++) {
            uint32_t ah[4], al[4];
            {
                float p00 = sc[2*kk][0],   p01 = sc[2*kk][1];
                float p10 = sc[2*kk][2],   p11 = sc[2*kk][3];
                float p20 = sc[2*kk+1][0], p21 = sc[2*kk+1][1];
                float p30 = sc[2*kk+1][2], p31 = sc[2*kk+1][3];
                ah[0] = pkh(p00, p01); ah[1] = pkh(p10, p11);
                ah[2] = pkh(p20, p21); ah[3] = pkh(p30, p31);
                float r00 = p00 - __half2float(__float2half(p00));
                float r01 = p01 - __half2float(__float2half(p01));
                float r10 = p10 - __half2float(__float2half(p10));
                float r11 = p11 - __half2float(__float2half(p11));
                float r20 = p20 - __half2float(__float2half(p20));
                float r21 = p21 - __half2float(__float2half(p21));
                float r30 = p30 - __half2float(__float2half(p30));
                float r31 = p31 - __half2float(__float2half(p31));
                al[0] = pkh(r00, r01); al[1] = pkh(r10, r11);
                al[2] = pkh(r20, r21); al[3] = pkh(r30, r31);
            }
            uint32_t vbf[8][2];
            #pragma unroll
            for (int np = 0; np < 4; np++)
                ldmx4t(vbf[2*np][0], vbf[2*np][1], vbf[2*np+1][0], vbf[2*np+1][1],
                       sb + VH_OFF + vrow + (uint32_t)(kk * 16 * TPAD + np * 16) * 2);
            #pragma unroll
            for (int nt = 0; nt < 8; nt++) hmma(oc[nt], ah, vbf[nt][0], vbf[nt][1]);
            #pragma unroll
            for (int nt = 0; nt < 8; nt++) hmma(oc[nt], al, vbf[nt][0], vbf[nt][1]);
            #pragma unroll
            for (int np = 0; np < 4; np++)
                ldmx4t(vbf[2*np][0], vbf[2*np][1], vbf[2*np+1][0], vbf[2*np+1][1],
                       sb + VL_OFF + vrow + (uint32_t)(kk * 16 * TPAD + np * 16) * 2);
            #pragma unroll
            for (int nt = 0; nt < 8; nt++) hmma(oc[nt], ah, vbf[nt][0], vbf[nt][1]);
        }
    }

    float inv0 = 1.f / l2[0], inv1 = 1.f / l2[1];
    int row0 = q0 + m0 + g;
    size_t r0b = ((size_t)b * S_LEN + row0) * K2 + h * DKH;
    size_t r1b = ((size_t)b * S_LEN + row0 + 8) * K2 + h * DKH;
    #pragma unroll
    for (int nt = 0; nt < 8; nt++) {
        int col = nt * 8 + 2 * t;
        #pragma unroll
        for (int half = 0; half < 2; half++) {
            float v0 = oc[nt][2*half]   * (half ? inv1 : inv0);
            float v1 = oc[nt][2*half+1] * (half ? inv1 : inv0);
            __half h0 = __float2half(v0);
            __half h1 = __float2half(v1);
            __half l0 = __float2half(v0 - __half2float(h0));
            __half l1 = __float2half(v1 - __half2float(h1));
            size_t base = (half ? r1b : r0b) + col;
            *(__half2*)&oa[base]           = __halves2half2(h0, h1);
            *(__half2*)&oa[base + D_MODEL] = __halves2half2(l0, l1);
        }
    }
}

// ---------------------------------------------------------------------------
extern "C" void kernel_launch(void* const* d_in, const int* in_sizes, int n_in,
                              void* d_out, int out_size)
{
    const float* x      = (const float*)d_in[0];
    const float* Wq     = (const float*)d_in[1];
    const float* Wk     = (const float*)d_in[2];
    const float* Wv     = (const float*)d_in[3];
    const float* Wo     = (const float*)d_in[4];
    const float* slopes = (const float*)d_in[5];
    float* out = (float*)d_out;

    __half *qh, *ql, *xa, *aoa, *wqkv, *wo;
    cudaGetSymbolAddress((void**)&qh,   g_qh);
    cudaGetSymbolAddress((void**)&ql,   g_ql);
    cudaGetSymbolAddress((void**)&xa,   g_xa);
    cudaGetSymbolAddress((void**)&aoa,  g_aoa);
    cudaGetSymbolAddress((void**)&wqkv, g_wqkv);
    cudaGetSymbolAddress((void**)&wo,   g_wo);

    cudaFuncSetAttribute((const void*)gemm_mma<true, D_MODEL>,
                         cudaFuncAttributeMaxDynamicSharedMemorySize, SMEM_GEMM);
    cudaFuncSetAttribute((const void*)gemm_mma<true, D_MODEL>,
                         cudaFuncAttributePreferredSharedMemoryCarveout, 100);
    cudaFuncSetAttribute((const void*)gemm_mma<false, K2>,
                         cudaFuncAttributeMaxDynamicSharedMemorySize, SMEM_GEMM);
    cudaFuncSetAttribute((const void*)gemm_mma<false, K2>,
                         cudaFuncAttributePreferredSharedMemoryCarveout, 100);
    cudaFuncSetAttribute(attn_tc, cudaFuncAttributeMaxDynamicSharedMemorySize,
                         SMEM_ATTN);
    cudaFuncSetAttribute(attn_tc, cudaFuncAttributePreferredSharedMemoryCarveout,
                         100);

    conv_plain<<<MROWS, 256>>>(x, xa);
    conv_w<<<dim3(D_MODEL, 4), 256>>>(Wq, Wk, Wv, Wo, wqkv, wo);

    // QKV projection (plain fp16, K=1024) -> fp16 hi/lo pair arrays
    gemm_mma<true, D_MODEL><<<dim3(NQKV / GBN, MROWS / GBM), 256, SMEM_GEMM>>>(
        xa, wqkv, nullptr, qh, ql, NQKV);

    // tensor-core attention -> split aoa directly
    attn_tc<<<dim3(S_LEN / BQ, NHEADS, BATCH), 128, SMEM_ATTN>>>(
        qh, ql, slopes, aoa);

    // output projection (split A, K=2048) -> fp32 result
    gemm_mma<false, K2><<<dim3(D_MODEL / GBN, MROWS / GBM), 256, SMEM_GEMM>>>(
        aoa, wo, out, nullptr, nullptr, D_MODEL);
}

// round 15
// speedup vs baseline: 1.8502x; 1.0300x over previous
#include <cuda_runtime.h>
#include <cuda_fp16.h>
#include <stdint.h>
#include <math.h>

#define S_LEN   2048
#define D_MODEL 1024
#define NHEADS  16
#define DKH     64
#define HALF_WIN 128
#define BQ      64
#define BATCH   2
#define MROWS   (BATCH * S_LEN)   // 4096
#define K2      (2 * D_MODEL)     // 2048
#define NQKV    3072

// ---------------- scratch (static device globals; no allocation) -----------
__device__ __half g_qh  [MROWS * NQKV];              // qkv hi (fp16)
__device__ __half g_ql  [MROWS * NQKV];              // qkv lo (fp16)
__device__ __half g_xa  [MROWS * D_MODEL];           // x plain fp16
__device__ __half g_aoa [MROWS * K2];                // attn-out split [hi|lo]
__device__ __half g_wqkv[NQKV * D_MODEL];            // [Wq;Wk;Wv] plain fp16
__device__ __half g_wo  [D_MODEL * K2];              // Wo split [hi|hi]

// ---------------- fp32 -> fp16 conversions (one fused launch) ---------------
// grid (4096, 2): y=0 -> x rows; y=1 -> weight rows (w = bx>>10, r = bx&1023)
__global__ __launch_bounds__(256) void conv_all(
    const float* __restrict__ x,
    const float* __restrict__ Wq, const float* __restrict__ Wk,
    const float* __restrict__ Wv, const float* __restrict__ Wo,
    __half* __restrict__ xa, __half* __restrict__ wqkv, __half* __restrict__ wo)
{
    int c = threadIdx.x * 4;
    if (blockIdx.y == 0) {
        int r = blockIdx.x;
        float4 v = *(const float4*)(x + (size_t)r * D_MODEL + c);
        __half2* o = (__half2*)(xa + (size_t)r * D_MODEL + c);
        o[0] = __halves2half2(__float2half(v.x), __float2half(v.y));
        o[1] = __halves2half2(__float2half(v.z), __float2half(v.w));
    } else {
        int w = blockIdx.x >> 10;
        int r = blockIdx.x & 1023;
        const float* src = (w == 0) ? Wq : (w == 1) ? Wk : (w == 2) ? Wv : Wo;
        float4 v = *(const float4*)(src + (size_t)r * D_MODEL + c);
        __half2 p0 = __halves2half2(__float2half(v.x), __float2half(v.y));
        __half2 p1 = __halves2half2(__float2half(v.z), __float2half(v.w));
        if (w < 3) {
            __half2* o = (__half2*)(wqkv + ((size_t)w * D_MODEL + r) * D_MODEL + c);
            o[0] = p0; o[1] = p1;
        } else {
            __half2* o0 = (__half2*)(wo + (size_t)r * K2 + c);
            __half2* o1 = (__half2*)(wo + (size_t)r * K2 + D_MODEL + c);
            o0[0] = p0; o0[1] = p1;
            o1[0] = p0; o1[1] = p1;
        }
    }
}

// ---------------- common PTX helpers ----------------------------------------
__device__ __forceinline__ uint32_t s2u(const void* p) {
    uint32_t a;
    asm("{ .reg .u64 t; cvta.to.shared.u64 t, %1; cvt.u32.u64 %0, t; }"
        : "=r"(a) : "l"(p));
    return a;
}
__device__ __forceinline__ void cp16(uint32_t dst, const void* src) {
    asm volatile("cp.async.cg.shared.global [%0], [%1], 16;" :: "r"(dst), "l"(src));
}
__device__ __forceinline__ void ldmx4(uint32_t& r0, uint32_t& r1, uint32_t& r2,
                                      uint32_t& r3, uint32_t addr) {
    asm volatile("ldmatrix.sync.aligned.m8n8.x4.shared.b16 {%0,%1,%2,%3}, [%4];"
                 : "=r"(r0), "=r"(r1), "=r"(r2), "=r"(r3) : "r"(addr));
}
__device__ __forceinline__ void ldmx4t(uint32_t& r0, uint32_t& r1, uint32_t& r2,
                                       uint32_t& r3, uint32_t addr) {
    asm volatile("ldmatrix.sync.aligned.m8n8.x4.trans.shared.b16 {%0,%1,%2,%3}, [%4];"
                 : "=r"(r0), "=r"(r1), "=r"(r2), "=r"(r3) : "r"(addr));
}
__device__ __forceinline__ void hmma(float* c, const uint32_t* a,
                                     uint32_t b0, uint32_t b1) {
    asm volatile(
        "mma.sync.aligned.m16n8k16.row.col.f32.f16.f16.f32 "
        "{%0,%1,%2,%3}, {%4,%5,%6,%7}, {%8,%9}, {%0,%1,%2,%3};"
        : "+f"(c[0]), "+f"(c[1]), "+f"(c[2]), "+f"(c[3])
        : "r"(a[0]), "r"(a[1]), "r"(a[2]), "r"(a[3]), "r"(b0), "r"(b1));
}
__device__ __forceinline__ uint32_t pkh(float x, float y) {
    __half2 r = __halves2half2(__float2half(x), __float2half(y));
    return *(uint32_t*)&r;
}

// ---------------- mma.sync fp16 GEMM (R13/R14 proven, unchanged) ------------
#define GBM 128
#define GBN 128
#define GBK 64
#define PADK 72
#define STG 3
#define SMEM_GEMM (STG * (GBM + GBN) * PADK * 2)   // 110592 B

template <bool SPLIT, int KD>
__global__ __launch_bounds__(256, 2) void gemm_mma(
    const __half* __restrict__ A,
    const __half* __restrict__ B,
    float* __restrict__ Yf,
    __half* __restrict__ Yh, __half* __restrict__ Yl, int N)
{
    extern __shared__ __half smem_g[];

    int tid = threadIdx.x;
    int wid = tid >> 5, lane = tid & 31;
    int wm = wid & 1, wn = wid >> 1;
    int bm = blockIdx.y * GBM, bn = blockIdx.x * GBN;
    int g = lane >> 2, tig = lane & 3;

    int lrow = tid >> 3;
    int lch  = tid & 7;

    uint32_t as_base = s2u(smem_g);
    uint32_t bs_base = as_base + STG * GBM * PADK * 2;

    uint32_t a_ld = as_base +
        ((uint32_t)(wm * 64 + (lane & 15)) * PADK + ((lane >> 4) * 8)) * 2;
    uint32_t b_ld = bs_base +
        ((uint32_t)(wn * 32 + (lane >> 4) * 8 + (lane & 7)) * PADK +
         (((lane >> 3) & 1) * 8)) * 2;

    const int NIT = KD / GBK;
    const uint32_t ASTG = GBM * PADK * 2;
    const uint32_t BSTG = GBN * PADK * 2;

#define LOAD_STAGE(s, k0)                                                     \
    do {                                                                      \
        _Pragma("unroll")                                                     \
        for (int i = 0; i < 4; i++) {                                         \
            int row = lrow + i * 32;                                          \
            cp16(as_base + (uint32_t)(s) * ASTG + (row * PADK + lch * 8) * 2, \
                 A + (size_t)(bm + row) * KD + (k0) + lch * 8);               \
            cp16(bs_base + (uint32_t)(s) * BSTG + (row * PADK + lch * 8) * 2, \
                 B + (size_t)(bn + row) * KD + (k0) + lch * 8);               \
        }                                                                     \
    } while (0)

    LOAD_STAGE(0, 0);
    asm volatile("cp.async.commit_group;");
    LOAD_STAGE(1, GBK);
    asm volatile("cp.async.commit_group;");

    float acc[4][4][4];
    #pragma unroll
    for (int i = 0; i < 4; i++)
        #pragma unroll
        for (int j = 0; j < 4; j++)
            #pragma unroll
            for (int t = 0; t < 4; t++) acc[i][j][t] = 0.f;

    int s = 0;
    for (int it = 0; it < NIT; it++) {
        asm volatile("cp.async.wait_group 1;");
        __syncthreads();

        uint32_t a_s = a_ld + s * ASTG;
        uint32_t b_s = b_ld + s * BSTG;

        #pragma unroll
        for (int kk = 0; kk < GBK; kk += 16) {
            uint32_t af[4][4], bf[4][2];
            #pragma unroll
            for (int i = 0; i < 4; i++)
                ldmx4(af[i][0], af[i][1], af[i][2], af[i][3],
                      a_s + (uint32_t)(i * 16 * PADK + kk) * 2);
            #pragma unroll
            for (int jp = 0; jp < 2; jp++)
                ldmx4(bf[2*jp][0], bf[2*jp][1], bf[2*jp+1][0], bf[2*jp+1][1],
                      b_s + (uint32_t)(jp * 16 * PADK + kk) * 2);
            #pragma unroll
            for (int i = 0; i < 4; i++)
                #pragma unroll
                for (int j = 0; j < 4; j++)
                    hmma(acc[i][j], af[i], bf[j][0], bf[j][1]);
        }

        int s2 = s + 2; if (s2 >= STG) s2 -= STG;
        if (it + 2 < NIT) LOAD_STAGE(s2, (it + 2) * GBK);
        asm volatile("cp.async.commit_group;");
        s = s + 1; if (s >= STG) s = 0;
    }

    if (SPLIT) {
        #pragma unroll
        for (int i = 0; i < 4; i++) {
            int r = bm + wm * 64 + i * 16 + g;
            #pragma unroll
            for (int j = 0; j < 4; j++) {
                int c = bn + wn * 32 + j * 8 + 2 * tig;
                #pragma unroll
                for (int half = 0; half < 2; half++) {
                    float v0 = acc[i][j][2*half], v1 = acc[i][j][2*half+1];
                    __half h0 = __float2half(v0);
                    __half h1 = __float2half(v1);
                    __half l0 = __float2half(v0 - __half2float(h0));
                    __half l1 = __float2half(v1 - __half2float(h1));
                    size_t idx = (size_t)(r + 8*half) * N + c;
                    *(__half2*)&Yh[idx] = __halves2half2(h0, h1);
                    *(__half2*)&Yl[idx] = __halves2half2(l0, l1);
                }
            }
        }
    } else {
        #pragma unroll
        for (int i = 0; i < 4; i++) {
            int r = bm + wm * 64 + i * 16 + g;
            #pragma unroll
            for (int j = 0; j < 4; j++) {
                int c = bn + wn * 32 + j * 8 + 2 * tig;
                *(float2*)&Yf[(size_t)r * N + c]       = make_float2(acc[i][j][0], acc[i][j][1]);
                *(float2*)&Yf[(size_t)(r + 8) * N + c] = make_float2(acc[i][j][2], acc[i][j][3]);
            }
        }
    }
#undef LOAD_STAGE
}

// ---------------- tensor-core windowed ALiBi flash attention ----------------
// R13 math, plus double-buffered cp.async K/V pipeline.
#define TPAD 72
#define TILE_BYTES (64 * TPAD * 2)     // 9216
#define QH_OFF 0
#define QL_OFF (1 * TILE_BYTES)
#define KV_BASE (2 * TILE_BYTES)
// per buffer: KH=+0, KL=+1, VH=+2, VL=+3 (tiles)
#define SMEM_ATTN (10 * TILE_BYTES)    // 92160

__device__ __forceinline__ void ldtile_async(
    uint32_t sm_off, const __half* __restrict__ gsrc, int tid)
{
    #pragma unroll
    for (int i = 0; i < 4; i++) {
        int idx = tid + i * 128;
        int row = idx >> 3, ch = idx & 7;
        cp16(sm_off + (uint32_t)(row * TPAD + ch * 8) * 2,
             gsrc + (size_t)row * NQKV + ch * 8);
    }
}

__global__ __launch_bounds__(128) void attn_tc(
    const __half* __restrict__ qkvh,
    const __half* __restrict__ qkvl,
    const float* __restrict__ slopes,
    __half* __restrict__ oa)
{
    extern __shared__ char smc[];
    uint32_t sb = s2u(smc);

    int qt = blockIdx.x, h = blockIdx.y, b = blockIdx.z;
    int q0 = qt * BQ;
    int tid = threadIdx.x, wid = tid >> 5, lane = tid & 31;
    int g = lane >> 2, t = lane & 3;
    int m0 = wid * 16;
    float slope = slopes[h];

    int kstart = q0 - HALF_WIN; if (kstart < 0) kstart = 0;
    int kend   = q0 + BQ + HALF_WIN; if (kend > S_LEN) kend = S_LEN;
    int nchunks = (kend - kstart) >> 6;

    // prologue: async-load Q tiles + first KV chunk as one group
    size_t qbase = ((size_t)b * S_LEN + q0) * NQKV + h * DKH;
    ldtile_async(sb + QH_OFF, qkvh + qbase, tid);
    ldtile_async(sb + QL_OFF, qkvl + qbase, tid);
    {
        size_t kb = ((size_t)b * S_LEN + kstart) * NQKV + D_MODEL + h * DKH;
        size_t vb = ((size_t)b * S_LEN + kstart) * NQKV + 2 * D_MODEL + h * DKH;
        uint32_t kv0 = sb + KV_BASE;
        ldtile_async(kv0 + 0 * TILE_BYTES, qkvh + kb, tid);
        ldtile_async(kv0 + 1 * TILE_BYTES, qkvl + kb, tid);
        ldtile_async(kv0 + 2 * TILE_BYTES, qkvh + vb, tid);
        ldtile_async(kv0 + 3 * TILE_BYTES, qkvl + vb, tid);
    }
    asm volatile("cp.async.commit_group;");
    asm volatile("cp.async.wait_group 0;");
    __syncthreads();

    // Q A-fragments (resident for the whole kernel)
    uint32_t arow = ((uint32_t)(m0 + (lane & 15)) * TPAD + ((lane >> 4) * 8)) * 2;
    uint32_t qh4[4][4], ql4[4][4];
    #pragma unroll
    for (int s = 0; s < 4; s++) {
        ldmx4(qh4[s][0], qh4[s][1], qh4[s][2], qh4[s][3],
              sb + QH_OFF + arow + s * 32);
        ldmx4(ql4[s][0], ql4[s][1], ql4[s][2], ql4[s][3],
              sb + QL_OFF + arow + s * 32);
    }

    float oc[8][4];
    #pragma unroll
    for (int nt = 0; nt < 8; nt++)
        #pragma unroll
        for (int e = 0; e < 4; e++) oc[nt][e] = 0.f;
    float m2[2] = {-INFINITY, -INFINITY};
    float l2[2] = {0.f, 0.f};

    uint32_t brow = (((uint32_t)((lane >> 4) * 8 + (lane & 7))) * TPAD +
                     ((lane >> 3) & 1) * 8) * 2;
    uint32_t vrow = (((uint32_t)(((lane >> 3) & 1) * 8 + (lane & 7))) * TPAD +
                     ((lane >> 4) * 8)) * 2;

    for (int ic = 0; ic < nchunks; ic++) {
        int kc = kstart + ic * 64;
        uint32_t kv = sb + KV_BASE + (uint32_t)(ic & 1) * 4 * TILE_BYTES;

        if (ic > 0) {
            asm volatile("cp.async.wait_group 0;");
            __syncthreads();   // also orders previous compute on this buffer
        }
        // prefetch next chunk into the other buffer (overlaps compute below)
        if (ic + 1 < nchunks) {
            int kn = kc + 64;
            size_t kb = ((size_t)b * S_LEN + kn) * NQKV + D_MODEL + h * DKH;
            size_t vb = ((size_t)b * S_LEN + kn) * NQKV + 2 * D_MODEL + h * DKH;
            uint32_t kvn = sb + KV_BASE + (uint32_t)((ic + 1) & 1) * 4 * TILE_BYTES;
            ldtile_async(kvn + 0 * TILE_BYTES, qkvh + kb, tid);
            ldtile_async(kvn + 1 * TILE_BYTES, qkvl + kb, tid);
            ldtile_async(kvn + 2 * TILE_BYTES, qkvh + vb, tid);
            ldtile_async(kvn + 3 * TILE_BYTES, qkvl + vb, tid);
            asm volatile("cp.async.commit_group;");
        }

        // ---- S = Q K^T (3-term) ----
        float sc[8][4];
        #pragma unroll
        for (int nt = 0; nt < 8; nt++)
            #pragma unroll
            for (int e = 0; e < 4; e++) sc[nt][e] = 0.f;

        #pragma unroll
        for (int s = 0; s < 4; s++) {
            uint32_t kbf[8][2];
            #pragma unroll
            for (int np = 0; np < 4; np++)
                ldmx4(kbf[2*np][0], kbf[2*np][1], kbf[2*np+1][0], kbf[2*np+1][1],
                      kv + 0 * TILE_BYTES + brow + (uint32_t)(np * 16 * TPAD) * 2 + s * 32);
            #pragma unroll
            for (int nt = 0; nt < 8; nt++) hmma(sc[nt], qh4[s], kbf[nt][0], kbf[nt][1]);
            #pragma unroll
            for (int nt = 0; nt < 8; nt++) hmma(sc[nt], ql4[s], kbf[nt][0], kbf[nt][1]);
            #pragma unroll
            for (int np = 0; np < 4; np++)
                ldmx4(kbf[2*np][0], kbf[2*np][1], kbf[2*np+1][0], kbf[2*np+1][1],
                      kv + 1 * TILE_BYTES + brow + (uint32_t)(np * 16 * TPAD) * 2 + s * 32);
            #pragma unroll
            for (int nt = 0; nt < 8; nt++) hmma(sc[nt], qh4[s], kbf[nt][0], kbf[nt][1]);
        }

        // ---- scale + ALiBi + window mask ----
        #pragma unroll
        for (int nt = 0; nt < 8; nt++) {
            #pragma unroll
            for (int e = 0; e < 4; e++) {
                int row = q0 + m0 + g + (e >= 2 ? 8 : 0);
                int col = kc + nt * 8 + 2 * t + (e & 1);
                int d = row - col;
                float sv = sc[nt][e] * 0.125f + slope * (float)d;
                if (d > HALF_WIN || d < -HALF_WIN) sv = -INFINITY;
                sc[nt][e] = sv;
            }
        }

        // ---- in-warp softmax ----
        #pragma unroll
        for (int half = 0; half < 2; half++) {
            float mx = -INFINITY;
            #pragma unroll
            for (int nt = 0; nt < 8; nt++)
                mx = fmaxf(mx, fmaxf(sc[nt][2*half], sc[nt][2*half+1]));
            mx = fmaxf(mx, __shfl_xor_sync(0xffffffffu, mx, 1));
            mx = fmaxf(mx, __shfl_xor_sync(0xffffffffu, mx, 2));
            float mnew = fmaxf(m2[half], mx);

            float alpha, lsum = 0.f;
            if (mnew == -INFINITY) {
                alpha = 1.f;
                #pragma unroll
                for (int nt = 0; nt < 8; nt++) {
                    sc[nt][2*half] = 0.f; sc[nt][2*half+1] = 0.f;
                }
            } else {
                alpha = __expf(m2[half] - mnew);
                #pragma unroll
                for (int nt = 0; nt < 8; nt++) {
                    float p0 = __expf(sc[nt][2*half]   - mnew);
                    float p1 = __expf(sc[nt][2*half+1] - mnew);
                    sc[nt][2*half] = p0; sc[nt][2*half+1] = p1;
                    lsum += p0 + p1;
                }
            }
            lsum += __shfl_xor_sync(0xffffffffu, lsum, 1);
            lsum += __shfl_xor_sync(0xffffffffu, lsum, 2);
            l2[half] = l2[half] * alpha + lsum;
            m2[half] = mnew;
            #pragma unroll
            for (int nt = 0; nt < 8; nt++) {
                oc[nt][2*half]   *= alpha;
                oc[nt][2*half+1] *= alpha;
            }
        }

        // ---- O += P V (3-term) ----
        #pragma unroll
        for (int kk = 0; kk < 4; kk++) {
            uint32_t ah[4], al[4];
            {
                float p00 = sc[2*kk][0],   p01 = sc[2*kk][1];
                float p10 = sc[2*kk][2],   p11 = sc[2*kk][3];
                float p20 = sc[2*kk+1][0], p21 = sc[2*kk+1][1];
                float p30 = sc[2*kk+1][2], p31 = sc[2*kk+1][3];
                ah[0] = pkh(p00, p01); ah[1] = pkh(p10, p11);
                ah[2] = pkh(p20, p21); ah[3] = pkh(p30, p31);
                float r00 = p00 - __half2float(__float2half(p00));
                float r01 = p01 - __half2float(__float2half(p01));
                float r10 = p10 - __half2float(__float2half(p10));
                float r11 = p11 - __half2float(__float2half(p11));
                float r20 = p20 - __half2float(__float2half(p20));
                float r21 = p21 - __half2float(__float2half(p21));
                float r30 = p30 - __half2float(__float2half(p30));
                float r31 = p31 - __half2float(__float2half(p31));
                al[0] = pkh(r00, r01); al[1] = pkh(r10, r11);
                al[2] = pkh(r20, r21); al[3] = pkh(r30, r31);
            }
            uint32_t vbf[8][2];
            #pragma unroll
            for (int np = 0; np < 4; np++)
                ldmx4t(vbf[2*np][0], vbf[2*np][1], vbf[2*np+1][0], vbf[2*np+1][1],
                       kv + 2 * TILE_BYTES + vrow + (uint32_t)(kk * 16 * TPAD + np * 16) * 2);
            #pragma unroll
            for (int nt = 0; nt < 8; nt++) hmma(oc[nt], ah, vbf[nt][0], vbf[nt][1]);
            #pragma unroll
            for (int nt = 0; nt < 8; nt++) hmma(oc[nt], al, vbf[nt][0], vbf[nt][1]);
            #pragma unroll
            for (int np = 0; np < 4; np++)
                ldmx4t(vbf[2*np][0], vbf[2*np][1], vbf[2*np+1][0], vbf[2*np+1][1],
                       kv + 3 * TILE_BYTES + vrow + (uint32_t)(kk * 16 * TPAD + np * 16) * 2);
            #pragma unroll
            for (int nt = 0; nt < 8; nt++) hmma(oc[nt], ah, vbf[nt][0], vbf[nt][1]);
        }
    }

    // epilogue: normalize + fp16 pair split write [hi | lo] into aoa
    float inv0 = 1.f / l2[0], inv1 = 1.f / l2[1];
    int row0 = q0 + m0 + g;
    size_t r0b = ((size_t)b * S_LEN + row0) * K2 + h * DKH;
    size_t r1b = ((size_t)b * S_LEN + row0 + 8) * K2 + h * DKH;
    #pragma unroll
    for (int nt = 0; nt < 8; nt++) {
        int col = nt * 8 + 2 * t;
        #pragma unroll
        for (int half = 0; half < 2; half++) {
            float v0 = oc[nt][2*half]   * (half ? inv1 : inv0);
            float v1 = oc[nt][2*half+1] * (half ? inv1 : inv0);
            __half h0 = __float2half(v0);
            __half h1 = __float2half(v1);
            __half l0 = __float2half(v0 - __half2float(h0));
            __half l1 = __float2half(v1 - __half2float(h1));
            size_t base = (half ? r1b : r0b) + col;
            *(__half2*)&oa[base]           = __halves2half2(h0, h1);
            *(__half2*)&oa[base + D_MODEL] = __halves2half2(l0, l1);
        }
    }
}

// ---------------------------------------------------------------------------
extern "C" void kernel_launch(void* const* d_in, const int* in_sizes, int n_in,
                              void* d_out, int out_size)
{
    const float* x      = (const float*)d_in[0];
    const float* Wq     = (const float*)d_in[1];
    const float* Wk     = (const float*)d_in[2];
    const float* Wv     = (const float*)d_in[3];
    const float* Wo     = (const float*)d_in[4];
    const float* slopes = (const float*)d_in[5];
    float* out = (float*)d_out;

    __half *qh, *ql, *xa, *aoa, *wqkv, *wo;
    cudaGetSymbolAddress((void**)&qh,   g_qh);
    cudaGetSymbolAddress((void**)&ql,   g_ql);
    cudaGetSymbolAddress((void**)&xa,   g_xa);
    cudaGetSymbolAddress((void**)&aoa,  g_aoa);
    cudaGetSymbolAddress((void**)&wqkv, g_wqkv);
    cudaGetSymbolAddress((void**)&wo,   g_wo);

    cudaFuncSetAttribute((const void*)gemm_mma<true, D_MODEL>,
                         cudaFuncAttributeMaxDynamicSharedMemorySize, SMEM_GEMM);
    cudaFuncSetAttribute((const void*)gemm_mma<true, D_MODEL>,
                         cudaFuncAttributePreferredSharedMemoryCarveout, 100);
    cudaFuncSetAttribute((const void*)gemm_mma<false, K2>,
                         cudaFuncAttributeMaxDynamicSharedMemorySize, SMEM_GEMM);
    cudaFuncSetAttribute((const void*)gemm_mma<false, K2>,
                         cudaFuncAttributePreferredSharedMemoryCarveout, 100);
    cudaFuncSetAttribute(attn_tc, cudaFuncAttributeMaxDynamicSharedMemorySize,
                         SMEM_ATTN);
    cudaFuncSetAttribute(attn_tc, cudaFuncAttributePreferredSharedMemoryCarveout,
                         100);

    conv_all<<<dim3(MROWS, 2), 256>>>(x, Wq, Wk, Wv, Wo, xa, wqkv, wo);

    // QKV projection (plain fp16, K=1024) -> fp16 hi/lo pair arrays
    gemm_mma<true, D_MODEL><<<dim3(NQKV / GBN, MROWS / GBM), 256, SMEM_GEMM>>>(
        xa, wqkv, nullptr, qh, ql, NQKV);

    // tensor-core attention (cp.async double-buffered) -> split aoa
    attn_tc<<<dim3(S_LEN / BQ, NHEADS, BATCH), 128, SMEM_ATTN>>>(
        qh, ql, slopes, aoa);

    // output projection (split A, K=2048) -> fp32 result
    gemm_mma<false, K2><<<dim3(D_MODEL / GBN, MROWS / GBM), 256, SMEM_GEMM>>>(
        aoa, wo, out, nullptr, nullptr, D_MODEL);
}

// round 16
// speedup vs baseline: 2.0671x; 1.1172x over previous
#include <cuda_runtime.h>
#include <cuda_fp16.h>
#include <stdint.h>
#include <math.h>

#define S_LEN   2048
#define D_MODEL 1024
#define NHEADS  16
#define DKH     64
#define HALF_WIN 128
#define BQ      64
#define BATCH   2
#define MROWS   (BATCH * S_LEN)   // 4096
#define K2      (2 * D_MODEL)     // 2048
#define NQKV    3072

// ---------------- scratch (static device globals; no allocation) -----------
__device__ __half g_qh  [MROWS * NQKV];              // qkv hi (fp16)
__device__ __half g_ql  [MROWS * NQKV];              // qkv lo (fp16)
__device__ __half g_xa  [MROWS * D_MODEL];           // x plain fp16
__device__ __half g_aoa [MROWS * D_MODEL];           // attn-out plain fp16
__device__ __half g_wqkv[NQKV * D_MODEL];            // [Wq;Wk;Wv] plain fp16
__device__ __half g_wo  [D_MODEL * D_MODEL];         // Wo plain fp16

// ---------------- fp32 -> fp16 conversions (one fused launch) ---------------
// grid (4096, 2): y=0 -> x rows; y=1 -> weight rows (w = bx>>10, r = bx&1023)
__global__ __launch_bounds__(256) void conv_all(
    const float* __restrict__ x,
    const float* __restrict__ Wq, const float* __restrict__ Wk,
    const float* __restrict__ Wv, const float* __restrict__ Wo,
    __half* __restrict__ xa, __half* __restrict__ wqkv, __half* __restrict__ wo)
{
    int c = threadIdx.x * 4;
    if (blockIdx.y == 0) {
        int r = blockIdx.x;
        float4 v = *(const float4*)(x + (size_t)r * D_MODEL + c);
        __half2* o = (__half2*)(xa + (size_t)r * D_MODEL + c);
        o[0] = __halves2half2(__float2half(v.x), __float2half(v.y));
        o[1] = __halves2half2(__float2half(v.z), __float2half(v.w));
    } else {
        int w = blockIdx.x >> 10;
        int r = blockIdx.x & 1023;
        const float* src = (w == 0) ? Wq : (w == 1) ? Wk : (w == 2) ? Wv : Wo;
        float4 v = *(const float4*)(src + (size_t)r * D_MODEL + c);
        __half2 p0 = __halves2half2(__float2half(v.x), __float2half(v.y));
        __half2 p1 = __halves2half2(__float2half(v.z), __float2half(v.w));
        __half* dst = (w == 3) ? wo : wqkv + (size_t)w * D_MODEL * D_MODEL;
        __half2* o = (__half2*)(dst + (size_t)r * D_MODEL + c);
        o[0] = p0; o[1] = p1;
    }
}

// ---------------- common PTX helpers ----------------------------------------
__device__ __forceinline__ uint32_t s2u(const void* p) {
    uint32_t a;
    asm("{ .reg .u64 t; cvta.to.shared.u64 t, %1; cvt.u32.u64 %0, t; }"
        : "=r"(a) : "l"(p));
    return a;
}
__device__ __forceinline__ void cp16(uint32_t dst, const void* src) {
    asm volatile("cp.async.cg.shared.global [%0], [%1], 16;" :: "r"(dst), "l"(src));
}
__device__ __forceinline__ void ldmx4(uint32_t& r0, uint32_t& r1, uint32_t& r2,
                                      uint32_t& r3, uint32_t addr) {
    asm volatile("ldmatrix.sync.aligned.m8n8.x4.shared.b16 {%0,%1,%2,%3}, [%4];"
                 : "=r"(r0), "=r"(r1), "=r"(r2), "=r"(r3) : "r"(addr));
}
__device__ __forceinline__ void ldmx4t(uint32_t& r0, uint32_t& r1, uint32_t& r2,
                                       uint32_t& r3, uint32_t addr) {
    asm volatile("ldmatrix.sync.aligned.m8n8.x4.trans.shared.b16 {%0,%1,%2,%3}, [%4];"
                 : "=r"(r0), "=r"(r1), "=r"(r2), "=r"(r3) : "r"(addr));
}
__device__ __forceinline__ void hmma(float* c, const uint32_t* a,
                                     uint32_t b0, uint32_t b1) {
    asm volatile(
        "mma.sync.aligned.m16n8k16.row.col.f32.f16.f16.f32 "
        "{%0,%1,%2,%3}, {%4,%5,%6,%7}, {%8,%9}, {%0,%1,%2,%3};"
        : "+f"(c[0]), "+f"(c[1]), "+f"(c[2]), "+f"(c[3])
        : "r"(a[0]), "r"(a[1]), "r"(a[2]), "r"(a[3]), "r"(b0), "r"(b1));
}
__device__ __forceinline__ uint32_t pkh(float x, float y) {
    __half2 r = __halves2half2(__float2half(x), __float2half(y));
    return *(uint32_t*)&r;
}

// ---------------- mma.sync fp16 GEMM (R13-R15 proven, unchanged) ------------
#define GBM 128
#define GBN 128
#define GBK 64
#define PADK 72
#define STG 3
#define SMEM_GEMM (STG * (GBM + GBN) * PADK * 2)   // 110592 B

template <bool SPLIT, int KD>
__global__ __launch_bounds__(256, 2) void gemm_mma(
    const __half* __restrict__ A,
    const __half* __restrict__ B,
    float* __restrict__ Yf,
    __half* __restrict__ Yh, __half* __restrict__ Yl, int N)
{
    extern __shared__ __half smem_g[];

    int tid = threadIdx.x;
    int wid = tid >> 5, lane = tid & 31;
    int wm = wid & 1, wn = wid >> 1;
    int bm = blockIdx.y * GBM, bn = blockIdx.x * GBN;
    int g = lane >> 2, tig = lane & 3;

    int lrow = tid >> 3;
    int lch  = tid & 7;

    uint32_t as_base = s2u(smem_g);
    uint32_t bs_base = as_base + STG * GBM * PADK * 2;

    uint32_t a_ld = as_base +
        ((uint32_t)(wm * 64 + (lane & 15)) * PADK + ((lane >> 4) * 8)) * 2;
    uint32_t b_ld = bs_base +
        ((uint32_t)(wn * 32 + (lane >> 4) * 8 + (lane & 7)) * PADK +
         (((lane >> 3) & 1) * 8)) * 2;

    const int NIT = KD / GBK;
    const uint32_t ASTG = GBM * PADK * 2;
    const uint32_t BSTG = GBN * PADK * 2;

#define LOAD_STAGE(s, k0)                                                     \
    do {                                                                      \
        _Pragma("unroll")                                                     \
        for (int i = 0; i < 4; i++) {                                         \
            int row = lrow + i * 32;                                          \
            cp16(as_base + (uint32_t)(s) * ASTG + (row * PADK + lch * 8) * 2, \
                 A + (size_t)(bm + row) * KD + (k0) + lch * 8);               \
            cp16(bs_base + (uint32_t)(s) * BSTG + (row * PADK + lch * 8) * 2, \
                 B + (size_t)(bn + row) * KD + (k0) + lch * 8);               \
        }                                                                     \
    } while (0)

    LOAD_STAGE(0, 0);
    asm volatile("cp.async.commit_group;");
    LOAD_STAGE(1, GBK);
    asm volatile("cp.async.commit_group;");

    float acc[4][4][4];
    #pragma unroll
    for (int i = 0; i < 4; i++)
        #pragma unroll
        for (int j = 0; j < 4; j++)
            #pragma unroll
            for (int t = 0; t < 4; t++) acc[i][j][t] = 0.f;

    int s = 0;
    for (int it = 0; it < NIT; it++) {
        asm volatile("cp.async.wait_group 1;");
        __syncthreads();

        uint32_t a_s = a_ld + s * ASTG;
        uint32_t b_s = b_ld + s * BSTG;

        #pragma unroll
        for (int kk = 0; kk < GBK; kk += 16) {
            uint32_t af[4][4], bf[4][2];
            #pragma unroll
            for (int i = 0; i < 4; i++)
                ldmx4(af[i][0], af[i][1], af[i][2], af[i][3],
                      a_s + (uint32_t)(i * 16 * PADK + kk) * 2);
            #pragma unroll
            for (int jp = 0; jp < 2; jp++)
                ldmx4(bf[2*jp][0], bf[2*jp][1], bf[2*jp+1][0], bf[2*jp+1][1],
                      b_s + (uint32_t)(jp * 16 * PADK + kk) * 2);
            #pragma unroll
            for (int i = 0; i < 4; i++)
                #pragma unroll
                for (int j = 0; j < 4; j++)
                    hmma(acc[i][j], af[i], bf[j][0], bf[j][1]);
        }

        int s2 = s + 2; if (s2 >= STG) s2 -= STG;
        if (it + 2 < NIT) LOAD_STAGE(s2, (it + 2) * GBK);
        asm volatile("cp.async.commit_group;");
        s = s + 1; if (s >= STG) s = 0;
    }

    if (SPLIT) {
        #pragma unroll
        for (int i = 0; i < 4; i++) {
            int r = bm + wm * 64 + i * 16 + g;
            #pragma unroll
            for (int j = 0; j < 4; j++) {
                int c = bn + wn * 32 + j * 8 + 2 * tig;
                #pragma unroll
                for (int half = 0; half < 2; half++) {
                    float v0 = acc[i][j][2*half], v1 = acc[i][j][2*half+1];
                    __half h0 = __float2half(v0);
                    __half h1 = __float2half(v1);
                    __half l0 = __float2half(v0 - __half2float(h0));
                    __half l1 = __float2half(v1 - __half2float(h1));
                    size_t idx = (size_t)(r + 8*half) * N + c;
                    *(__half2*)&Yh[idx] = __halves2half2(h0, h1);
                    *(__half2*)&Yl[idx] = __halves2half2(l0, l1);
                }
            }
        }
    } else {
        #pragma unroll
        for (int i = 0; i < 4; i++) {
            int r = bm + wm * 64 + i * 16 + g;
            #pragma unroll
            for (int j = 0; j < 4; j++) {
                int c = bn + wn * 32 + j * 8 + 2 * tig;
                *(float2*)&Yf[(size_t)r * N + c]       = make_float2(acc[i][j][0], acc[i][j][1]);
                *(float2*)&Yf[(size_t)(r + 8) * N + c] = make_float2(acc[i][j][2], acc[i][j][3]);
            }
        }
    }
#undef LOAD_STAGE
}

// ---------------- tensor-core windowed ALiBi flash attention ----------------
// R15-proven: cp.async double-buffered KV pipeline; plain-fp16 output now.
#define TPAD 72
#define TILE_BYTES (64 * TPAD * 2)     // 9216
#define QH_OFF 0
#define QL_OFF (1 * TILE_BYTES)
#define KV_BASE (2 * TILE_BYTES)
#define SMEM_ATTN (10 * TILE_BYTES)    // 92160

__device__ __forceinline__ void ldtile_async(
    uint32_t sm_off, const __half* __restrict__ gsrc, int tid)
{
    #pragma unroll
    for (int i = 0; i < 4; i++) {
        int idx = tid + i * 128;
        int row = idx >> 3, ch = idx & 7;
        cp16(sm_off + (uint32_t)(row * TPAD + ch * 8) * 2,
             gsrc + (size_t)row * NQKV + ch * 8);
    }
}

__global__ __launch_bounds__(128) void attn_tc(
    const __half* __restrict__ qkvh,
    const __half* __restrict__ qkvl,
    const float* __restrict__ slopes,
    __half* __restrict__ oa)
{
    extern __shared__ char smc[];
    uint32_t sb = s2u(smc);

    int qt = blockIdx.x, h = blockIdx.y, b = blockIdx.z;
    int q0 = qt * BQ;
    int tid = threadIdx.x, wid = tid >> 5, lane = tid & 31;
    int g = lane >> 2, t = lane & 3;
    int m0 = wid * 16;
    float slope = slopes[h];

    int kstart = q0 - HALF_WIN; if (kstart < 0) kstart = 0;
    int kend   = q0 + BQ + HALF_WIN; if (kend > S_LEN) kend = S_LEN;
    int nchunks = (kend - kstart) >> 6;

    size_t qbase = ((size_t)b * S_LEN + q0) * NQKV + h * DKH;
    ldtile_async(sb + QH_OFF, qkvh + qbase, tid);
    ldtile_async(sb + QL_OFF, qkvl + qbase, tid);
    {
        size_t kb = ((size_t)b * S_LEN + kstart) * NQKV + D_MODEL + h * DKH;
        size_t vb = ((size_t)b * S_LEN + kstart) * NQKV + 2 * D_MODEL + h * DKH;
        uint32_t kv0 = sb + KV_BASE;
        ldtile_async(kv0 + 0 * TILE_BYTES, qkvh + kb, tid);
        ldtile_async(kv0 + 1 * TILE_BYTES, qkvl + kb, tid);
        ldtile_async(kv0 + 2 * TILE_BYTES, qkvh + vb, tid);
        ldtile_async(kv0 + 3 * TILE_BYTES, qkvl + vb, tid);
    }
    asm volatile("cp.async.commit_group;");
    asm volatile("cp.async.wait_group 0;");
    __syncthreads();

    uint32_t arow = ((uint32_t)(m0 + (lane & 15)) * TPAD + ((lane >> 4) * 8)) * 2;
    uint32_t qh4[4][4], ql4[4][4];
    #pragma unroll
    for (int s = 0; s < 4; s++) {
        ldmx4(qh4[s][0], qh4[s][1], qh4[s][2], qh4[s][3],
              sb + QH_OFF + arow + s * 32);
        ldmx4(ql4[s][0], ql4[s][1], ql4[s][2], ql4[s][3],
              sb + QL_OFF + arow + s * 32);
    }

    float oc[8][4];
    #pragma unroll
    for (int nt = 0; nt < 8; nt++)
        #pragma unroll
        for (int e = 0; e < 4; e++) oc[nt][e] = 0.f;
    float m2[2] = {-INFINITY, -INFINITY};
    float l2[2] = {0.f, 0.f};

    uint32_t brow = (((uint32_t)((lane >> 4) * 8 + (lane & 7))) * TPAD +
                     ((lane >> 3) & 1) * 8) * 2;
    uint32_t vrow = (((uint32_t)(((lane >> 3) & 1) * 8 + (lane & 7))) * TPAD +
                     ((lane >> 4) * 8)) * 2;

    for (int ic = 0; ic < nchunks; ic++) {
        int kc = kstart + ic * 64;
        uint32_t kv = sb + KV_BASE + (uint32_t)(ic & 1) * 4 * TILE_BYTES;

        if (ic > 0) {
            asm volatile("cp.async.wait_group 0;");
            __syncthreads();
        }
        if (ic + 1 < nchunks) {
            int kn = kc + 64;
            size_t kb = ((size_t)b * S_LEN + kn) * NQKV + D_MODEL + h * DKH;
            size_t vb = ((size_t)b * S_LEN + kn) * NQKV + 2 * D_MODEL + h * DKH;
            uint32_t kvn = sb + KV_BASE + (uint32_t)((ic + 1) & 1) * 4 * TILE_BYTES;
            ldtile_async(kvn + 0 * TILE_BYTES, qkvh + kb, tid);
            ldtile_async(kvn + 1 * TILE_BYTES, qkvl + kb, tid);
            ldtile_async(kvn + 2 * TILE_BYTES, qkvh + vb, tid);
            ldtile_async(kvn + 3 * TILE_BYTES, qkvl + vb, tid);
            asm volatile("cp.async.commit_group;");
        }

        float sc[8][4];
        #pragma unroll
        for (int nt = 0; nt < 8; nt++)
            #pragma unroll
            for (int e = 0; e < 4; e++) sc[nt][e] = 0.f;

        #pragma unroll
        for (int s = 0; s < 4; s++) {
            uint32_t kbf[8][2];
            #pragma unroll
            for (int np = 0; np < 4; np++)
                ldmx4(kbf[2*np][0], kbf[2*np][1], kbf[2*np+1][0], kbf[2*np+1][1],
                      kv + 0 * TILE_BYTES + brow + (uint32_t)(np * 16 * TPAD) * 2 + s * 32);
            #pragma unroll
            for (int nt = 0; nt < 8; nt++) hmma(sc[nt], qh4[s], kbf[nt][0], kbf[nt][1]);
            #pragma unroll
            for (int nt = 0; nt < 8; nt++) hmma(sc[nt], ql4[s], kbf[nt][0], kbf[nt][1]);
            #pragma unroll
            for (int np = 0; np < 4; np++)
                ldmx4(kbf[2*np][0], kbf[2*np][1], kbf[2*np+1][0], kbf[2*np+1][1],
                      kv + 1 * TILE_BYTES + brow + (uint32_t)(np * 16 * TPAD) * 2 + s * 32);
            #pragma unroll
            for (int nt = 0; nt < 8; nt++) hmma(sc[nt], qh4[s], kbf[nt][0], kbf[nt][1]);
        }

        #pragma unroll
        for (int nt = 0; nt < 8; nt++) {
            #pragma unroll
            for (int e = 0; e < 4; e++) {
                int row = q0 + m0 + g + (e >= 2 ? 8 : 0);
                int col = kc + nt * 8 + 2 * t + (e & 1);
                int d = row - col;
                float sv = sc[nt][e] * 0.125f + slope * (float)d;
                if (d > HALF_WIN || d < -HALF_WIN) sv = -INFINITY;
                sc[nt][e] = sv;
            }
        }

        #pragma unroll
        for (int half = 0; half < 2; half++) {
            float mx = -INFINITY;
            #pragma unroll
            for (int nt = 0; nt < 8; nt++)
                mx = fmaxf(mx, fmaxf(sc[nt][2*half], sc[nt][2*half+1]));
            mx = fmaxf(mx, __shfl_xor_sync(0xffffffffu, mx, 1));
            mx = fmaxf(mx, __shfl_xor_sync(0xffffffffu, mx, 2));
            float mnew = fmaxf(m2[half], mx);

            float alpha, lsum = 0.f;
            if (mnew == -INFINITY) {
                alpha = 1.f;
                #pragma unroll
                for (int nt = 0; nt < 8; nt++) {
                    sc[nt][2*half] = 0.f; sc[nt][2*half+1] = 0.f;
                }
            } else {
                alpha = __expf(m2[half] - mnew);
                #pragma unroll
                for (int nt = 0; nt < 8; nt++) {
                    float p0 = __expf(sc[nt][2*half]   - mnew);
                    float p1 = __expf(sc[nt][2*half+1] - mnew);
                    sc[nt][2*half] = p0; sc[nt][2*half+1] = p1;
                    lsum += p0 + p1;
                }
            }
            lsum += __shfl_xor_sync(0xffffffffu, lsum, 1);
            lsum += __shfl_xor_sync(0xffffffffu, lsum, 2);
            l2[half] = l2[half] * alpha + lsum;
            m2[half] = mnew;
            #pragma unroll
            for (int nt = 0; nt < 8; nt++) {
                oc[nt][2*half]   *= alpha;
                oc[nt][2*half+1] *= alpha;
            }
        }

        #pragma unroll
        for (int kk = 0; kk < 4; kk++) {
            uint32_t ah[4], al[4];
            {
                float p00 = sc[2*kk][0],   p01 = sc[2*kk][1];
                float p10 = sc[2*kk][2],   p11 = sc[2*kk][3];
                float p20 = sc[2*kk+1][0], p21 = sc[2*kk+1][1];
                float p30 = sc[2*kk+1][2], p31 = sc[2*kk+1][3];
                ah[0] = pkh(p00, p01); ah[1] = pkh(p10, p11);
                ah[2] = pkh(p20, p21); ah[3] = pkh(p30, p31);
                float r00 = p00 - __half2float(__float2half(p00));
                float r01 = p01 - __half2float(__float2half(p01));
                float r10 = p10 - __half2float(__float2half(p10));
                float r11 = p11 - __half2float(__float2half(p11));
                float r20 = p20 - __half2float(__float2half(p20));
                float r21 = p21 - __half2float(__float2half(p21));
                float r30 = p30 - __half2float(__float2half(p30));
                float r31 = p31 - __half2float(__float2half(p31));
                al[0] = pkh(r00, r01); al[1] = pkh(r10, r11);
                al[2] = pkh(r20, r21); al[3] = pkh(r30, r31);
            }
            uint32_t vbf[8][2];
            #pragma unroll
            for (int np = 0; np < 4; np++)
                ldmx4t(vbf[2*np][0], vbf[2*np][1], vbf[2*np+1][0], vbf[2*np+1][1],
                       kv + 2 * TILE_BYTES + vrow + (uint32_t)(kk * 16 * TPAD + np * 16) * 2);
            #pragma unroll
            for (int nt = 0; nt < 8; nt++) hmma(oc[nt], ah, vbf[nt][0], vbf[nt][1]);
            #pragma unroll
            for (int nt = 0; nt < 8; nt++) hmma(oc[nt], al, vbf[nt][0], vbf[nt][1]);
            #pragma unroll
            for (int np = 0; np < 4; np++)
                ldmx4t(vbf[2*np][0], vbf[2*np][1], vbf[2*np+1][0], vbf[2*np+1][1],
                       kv + 3 * TILE_BYTES + vrow + (uint32_t)(kk * 16 * TPAD + np * 16) * 2);
            #pragma unroll
            for (int nt = 0; nt < 8; nt++) hmma(oc[nt], ah, vbf[nt][0], vbf[nt][1]);
        }
    }

    // epilogue: normalize + plain fp16 write into aoa (D_MODEL-wide)
    float inv0 = 1.f / l2[0], inv1 = 1.f / l2[1];
    int row0 = q0 + m0 + g;
    size_t r0b = ((size_t)b * S_LEN + row0) * D_MODEL + h * DKH;
    size_t r1b = ((size_t)b * S_LEN + row0 + 8) * D_MODEL + h * DKH;
    #pragma unroll
    for (int nt = 0; nt < 8; nt++) {
        int col = nt * 8 + 2 * t;
        #pragma unroll
        for (int half = 0; half < 2; half++) {
            float v0 = oc[nt][2*half]   * (half ? inv1 : inv0);
            float v1 = oc[nt][2*half+1] * (half ? inv1 : inv0);
            size_t base = (half ? r1b : r0b) + col;
            *(__half2*)&oa[base] = __halves2half2(__float2half(v0), __float2half(v1));
        }
    }
}

// ---------------------------------------------------------------------------
extern "C" void kernel_launch(void* const* d_in, const int* in_sizes, int n_in,
                              void* d_out, int out_size)
{
    const float* x      = (const float*)d_in[0];
    const float* Wq     = (const float*)d_in[1];
    const float* Wk     = (const float*)d_in[2];
    const float* Wv     = (const float*)d_in[3];
    const float* Wo     = (const float*)d_in[4];
    const float* slopes = (const float*)d_in[5];
    float* out = (float*)d_out;

    __half *qh, *ql, *xa, *aoa, *wqkv, *wo;
    cudaGetSymbolAddress((void**)&qh,   g_qh);
    cudaGetSymbolAddress((void**)&ql,   g_ql);
    cudaGetSymbolAddress((void**)&xa,   g_xa);
    cudaGetSymbolAddress((void**)&aoa,  g_aoa);
    cudaGetSymbolAddress((void**)&wqkv, g_wqkv);
    cudaGetSymbolAddress((void**)&wo,   g_wo);

    cudaFuncSetAttribute((const void*)gemm_mma<true, D_MODEL>,
                         cudaFuncAttributeMaxDynamicSharedMemorySize, SMEM_GEMM);
    cudaFuncSetAttribute((const void*)gemm_mma<true, D_MODEL>,
                         cudaFuncAttributePreferredSharedMemoryCarveout, 100);
    cudaFuncSetAttribute((const void*)gemm_mma<false, D_MODEL>,
                         cudaFuncAttributeMaxDynamicSharedMemorySize, SMEM_GEMM);
    cudaFuncSetAttribute((const void*)gemm_mma<false, D_MODEL>,
                         cudaFuncAttributePreferredSharedMemoryCarveout, 100);
    cudaFuncSetAttribute(attn_tc, cudaFuncAttributeMaxDynamicSharedMemorySize,
                         SMEM_ATTN);
    cudaFuncSetAttribute(attn_tc, cudaFuncAttributePreferredSharedMemoryCarveout,
                         100);

    conv_all<<<dim3(MROWS, 2), 256>>>(x, Wq, Wk, Wv, Wo, xa, wqkv, wo);

    // QKV projection (plain fp16, K=1024) -> fp16 hi/lo pair arrays
    gemm_mma<true, D_MODEL><<<dim3(NQKV / GBN, MROWS / GBM), 256, SMEM_GEMM>>>(
        xa, wqkv, nullptr, qh, ql, NQKV);

    // tensor-core attention (cp.async double-buffered) -> plain fp16 aoa
    attn_tc<<<dim3(S_LEN / BQ, NHEADS, BATCH), 128, SMEM_ATTN>>>(
        qh, ql, slopes, aoa);

    // output projection (plain fp16, K=1024) -> fp32 result
    gemm_mma<false, D_MODEL><<<dim3(D_MODEL / GBN, MROWS / GBM), 256, SMEM_GEMM>>>(
        aoa, wo, out, nullptr, nullptr, D_MODEL);
}

// round 17
// speedup vs baseline: 2.2923x; 1.1089x over previous
#include <cuda_runtime.h>
#include <cuda_fp16.h>
#include <stdint.h>
#include <math.h>

#define S_LEN   2048
#define D_MODEL 1024
#define NHEADS  16
#define DKH     64
#define HALF_WIN 128
#define BQ      64
#define BATCH   2
#define MROWS   (BATCH * S_LEN)   // 4096
#define NQKV    3072

// ---------------- scratch (static device globals; no allocation) -----------
__device__ __half g_qh  [MROWS * NQKV];              // qkv hi (fp16)
__device__ __half g_ql  [MROWS * NQKV];              // qkv lo (fp16)
__device__ __half g_xa  [MROWS * D_MODEL];           // x plain fp16
__device__ __half g_aoa [MROWS * D_MODEL];           // attn-out plain fp16
__device__ __half g_wqkv[NQKV * D_MODEL];            // [Wq;Wk;Wv] plain fp16
__device__ __half g_wo  [D_MODEL * D_MODEL];         // Wo plain fp16

// ---------------- fp32 -> fp16 conversions (one fused launch) ---------------
__global__ __launch_bounds__(256) void conv_all(
    const float* __restrict__ x,
    const float* __restrict__ Wq, const float* __restrict__ Wk,
    const float* __restrict__ Wv, const float* __restrict__ Wo,
    __half* __restrict__ xa, __half* __restrict__ wqkv, __half* __restrict__ wo)
{
    int c = threadIdx.x * 4;
    if (blockIdx.y == 0) {
        int r = blockIdx.x;
        float4 v = *(const float4*)(x + (size_t)r * D_MODEL + c);
        __half2* o = (__half2*)(xa + (size_t)r * D_MODEL + c);
        o[0] = __halves2half2(__float2half(v.x), __float2half(v.y));
        o[1] = __halves2half2(__float2half(v.z), __float2half(v.w));
    } else {
        int w = blockIdx.x >> 10;
        int r = blockIdx.x & 1023;
        const float* src = (w == 0) ? Wq : (w == 1) ? Wk : (w == 2) ? Wv : Wo;
        float4 v = *(const float4*)(src + (size_t)r * D_MODEL + c);
        __half2 p0 = __halves2half2(__float2half(v.x), __float2half(v.y));
        __half2 p1 = __halves2half2(__float2half(v.z), __float2half(v.w));
        __half* dst = (w == 3) ? wo : wqkv + (size_t)w * D_MODEL * D_MODEL;
        __half2* o = (__half2*)(dst + (size_t)r * D_MODEL + c);
        o[0] = p0; o[1] = p1;
    }
}

// ---------------- common PTX helpers ----------------------------------------
__device__ __forceinline__ uint32_t s2u(const void* p) {
    uint32_t a;
    asm("{ .reg .u64 t; cvta.to.shared.u64 t, %1; cvt.u32.u64 %0, t; }"
        : "=r"(a) : "l"(p));
    return a;
}
__device__ __forceinline__ void cp16(uint32_t dst, const void* src) {
    asm volatile("cp.async.cg.shared.global [%0], [%1], 16;" :: "r"(dst), "l"(src));
}
__device__ __forceinline__ void ldmx4(uint32_t& r0, uint32_t& r1, uint32_t& r2,
                                      uint32_t& r3, uint32_t addr) {
    asm volatile("ldmatrix.sync.aligned.m8n8.x4.shared.b16 {%0,%1,%2,%3}, [%4];"
                 : "=r"(r0), "=r"(r1), "=r"(r2), "=r"(r3) : "r"(addr));
}
__device__ __forceinline__ void ldmx4t(uint32_t& r0, uint32_t& r1, uint32_t& r2,
                                       uint32_t& r3, uint32_t addr) {
    asm volatile("ldmatrix.sync.aligned.m8n8.x4.trans.shared.b16 {%0,%1,%2,%3}, [%4];"
                 : "=r"(r0), "=r"(r1), "=r"(r2), "=r"(r3) : "r"(addr));
}
__device__ __forceinline__ void hmma(float* c, const uint32_t* a,
                                     uint32_t b0, uint32_t b1) {
    asm volatile(
        "mma.sync.aligned.m16n8k16.row.col.f32.f16.f16.f32 "
        "{%0,%1,%2,%3}, {%4,%5,%6,%7}, {%8,%9}, {%0,%1,%2,%3};"
        : "+f"(c[0]), "+f"(c[1]), "+f"(c[2]), "+f"(c[3])
        : "r"(a[0]), "r"(a[1]), "r"(a[2]), "r"(a[3]), "r"(b0), "r"(b1));
}
__device__ __forceinline__ uint32_t pkh(float x, float y) {
    __half2 r = __halves2half2(__float2half(x), __float2half(y));
    return *(uint32_t*)&r;
}

// ---------------- mma.sync fp16 GEMM (R13-R16 proven, unchanged) ------------
#define GBM 128
#define GBN 128
#define GBK 64
#define PADK 72
#define STG 3
#define SMEM_GEMM (STG * (GBM + GBN) * PADK * 2)   // 110592 B

template <bool SPLIT, int KD>
__global__ __launch_bounds__(256, 2) void gemm_mma(
    const __half* __restrict__ A,
    const __half* __restrict__ B,
    float* __restrict__ Yf,
    __half* __restrict__ Yh, __half* __restrict__ Yl, int N)
{
    extern __shared__ __half smem_g[];

    int tid = threadIdx.x;
    int wid = tid >> 5, lane = tid & 31;
    int wm = wid & 1, wn = wid >> 1;
    int bm = blockIdx.y * GBM, bn = blockIdx.x * GBN;
    int g = lane >> 2, tig = lane & 3;

    int lrow = tid >> 3;
    int lch  = tid & 7;

    uint32_t as_base = s2u(smem_g);
    uint32_t bs_base = as_base + STG * GBM * PADK * 2;

    uint32_t a_ld = as_base +
        ((uint32_t)(wm * 64 + (lane & 15)) * PADK + ((lane >> 4) * 8)) * 2;
    uint32_t b_ld = bs_base +
        ((uint32_t)(wn * 32 + (lane >> 4) * 8 + (lane & 7)) * PADK +
         (((lane >> 3) & 1) * 8)) * 2;

    const int NIT = KD / GBK;
    const uint32_t ASTG = GBM * PADK * 2;
    const uint32_t BSTG = GBN * PADK * 2;

#define LOAD_STAGE(s, k0)                                                     \
    do {                                                                      \
        _Pragma("unroll")                                                     \
        for (int i = 0; i < 4; i++) {                                         \
            int row = lrow + i * 32;                                          \
            cp16(as_base + (uint32_t)(s) * ASTG + (row * PADK + lch * 8) * 2, \
                 A + (size_t)(bm + row) * KD + (k0) + lch * 8);               \
            cp16(bs_base + (uint32_t)(s) * BSTG + (row * PADK + lch * 8) * 2, \
                 B + (size_t)(bn + row) * KD + (k0) + lch * 8);               \
        }                                                                     \
    } while (0)

    LOAD_STAGE(0, 0);
    asm volatile("cp.async.commit_group;");
    LOAD_STAGE(1, GBK);
    asm volatile("cp.async.commit_group;");

    float acc[4][4][4];
    #pragma unroll
    for (int i = 0; i < 4; i++)
        #pragma unroll
        for (int j = 0; j < 4; j++)
            #pragma unroll
            for (int t = 0; t < 4; t++) acc[i][j][t] = 0.f;

    int s = 0;
    for (int it = 0; it < NIT; it++) {
        asm volatile("cp.async.wait_group 1;");
        __syncthreads();

        uint32_t a_s = a_ld + s * ASTG;
        uint32_t b_s = b_ld + s * BSTG;

        #pragma unroll
        for (int kk = 0; kk < GBK; kk += 16) {
            uint32_t af[4][4], bf[4][2];
            #pragma unroll
            for (int i = 0; i < 4; i++)
                ldmx4(af[i][0], af[i][1], af[i][2], af[i][3],
                      a_s + (uint32_t)(i * 16 * PADK + kk) * 2);
            #pragma unroll
            for (int jp = 0; jp < 2; jp++)
                ldmx4(bf[2*jp][0], bf[2*jp][1], bf[2*jp+1][0], bf[2*jp+1][1],
                      b_s + (uint32_t)(jp * 16 * PADK + kk) * 2);
            #pragma unroll
            for (int i = 0; i < 4; i++)
                #pragma unroll
                for (int j = 0; j < 4; j++)
                    hmma(acc[i][j], af[i], bf[j][0], bf[j][1]);
        }

        int s2 = s + 2; if (s2 >= STG) s2 -= STG;
        if (it + 2 < NIT) LOAD_STAGE(s2, (it + 2) * GBK);
        asm volatile("cp.async.commit_group;");
        s = s + 1; if (s >= STG) s = 0;
    }

    if (SPLIT) {
        #pragma unroll
        for (int i = 0; i < 4; i++) {
            int r = bm + wm * 64 + i * 16 + g;
            #pragma unroll
            for (int j = 0; j < 4; j++) {
                int c = bn + wn * 32 + j * 8 + 2 * tig;
                #pragma unroll
                for (int half = 0; half < 2; half++) {
                    float v0 = acc[i][j][2*half], v1 = acc[i][j][2*half+1];
                    __half h0 = __float2half(v0);
                    __half h1 = __float2half(v1);
                    __half l0 = __float2half(v0 - __half2float(h0));
                    __half l1 = __float2half(v1 - __half2float(h1));
                    size_t idx = (size_t)(r + 8*half) * N + c;
                    *(__half2*)&Yh[idx] = __halves2half2(h0, h1);
                    *(__half2*)&Yl[idx] = __halves2half2(l0, l1);
                }
            }
        }
    } else {
        #pragma unroll
        for (int i = 0; i < 4; i++) {
            int r = bm + wm * 64 + i * 16 + g;
            #pragma unroll
            for (int j = 0; j < 4; j++) {
                int c = bn + wn * 32 + j * 8 + 2 * tig;
                *(float2*)&Yf[(size_t)r * N + c]       = make_float2(acc[i][j][0], acc[i][j][1]);
                *(float2*)&Yf[(size_t)(r + 8) * N + c] = make_float2(acc[i][j][2], acc[i][j][3]);
            }
        }
    }
#undef LOAD_STAGE
}

// ---------------- tensor-core windowed ALiBi flash attention ----------------
// QK: 3-term (qh*kh + ql*kh + qh*kl). PV: 1-term (ph*vh).
// cp.async double-buffered KV pipeline (3 tiles/chunk: Kh, Kl, Vh).
#define TPAD 72
#define TILE_BYTES (64 * TPAD * 2)     // 9216
#define QH_OFF 0
#define QL_OFF (1 * TILE_BYTES)
#define KV_BASE (2 * TILE_BYTES)
// per buffer: KH=+0, KL=+1, VH=+2
#define SMEM_ATTN (8 * TILE_BYTES)     // 73728

__device__ __forceinline__ void ldtile_async(
    uint32_t sm_off, const __half* __restrict__ gsrc, int tid)
{
    #pragma unroll
    for (int i = 0; i < 4; i++) {
        int idx = tid + i * 128;
        int row = idx >> 3, ch = idx & 7;
        cp16(sm_off + (uint32_t)(row * TPAD + ch * 8) * 2,
             gsrc + (size_t)row * NQKV + ch * 8);
    }
}

__global__ __launch_bounds__(128) void attn_tc(
    const __half* __restrict__ qkvh,
    const __half* __restrict__ qkvl,
    const float* __restrict__ slopes,
    __half* __restrict__ oa)
{
    extern __shared__ char smc[];
    uint32_t sb = s2u(smc);

    int qt = blockIdx.x, h = blockIdx.y, b = blockIdx.z;
    int q0 = qt * BQ;
    int tid = threadIdx.x, wid = tid >> 5, lane = tid & 31;
    int g = lane >> 2, t = lane & 3;
    int m0 = wid * 16;
    float slope = slopes[h];

    int kstart = q0 - HALF_WIN; if (kstart < 0) kstart = 0;
    int kend   = q0 + BQ + HALF_WIN; if (kend > S_LEN) kend = S_LEN;
    int nchunks = (kend - kstart) >> 6;

    size_t qbase = ((size_t)b * S_LEN + q0) * NQKV + h * DKH;
    ldtile_async(sb + QH_OFF, qkvh + qbase, tid);
    ldtile_async(sb + QL_OFF, qkvl + qbase, tid);
    {
        size_t kb = ((size_t)b * S_LEN + kstart) * NQKV + D_MODEL + h * DKH;
        size_t vb = ((size_t)b * S_LEN + kstart) * NQKV + 2 * D_MODEL + h * DKH;
        uint32_t kv0 = sb + KV_BASE;
        ldtile_async(kv0 + 0 * TILE_BYTES, qkvh + kb, tid);
        ldtile_async(kv0 + 1 * TILE_BYTES, qkvl + kb, tid);
        ldtile_async(kv0 + 2 * TILE_BYTES, qkvh + vb, tid);
    }
    asm volatile("cp.async.commit_group;");
    asm volatile("cp.async.wait_group 0;");
    __syncthreads();

    uint32_t arow = ((uint32_t)(m0 + (lane & 15)) * TPAD + ((lane >> 4) * 8)) * 2;
    uint32_t qh4[4][4], ql4[4][4];
    #pragma unroll
    for (int s = 0; s < 4; s++) {
        ldmx4(qh4[s][0], qh4[s][1], qh4[s][2], qh4[s][3],
              sb + QH_OFF + arow + s * 32);
        ldmx4(ql4[s][0], ql4[s][1], ql4[s][2], ql4[s][3],
              sb + QL_OFF + arow + s * 32);
    }

    float oc[8][4];
    #pragma unroll
    for (int nt = 0; nt < 8; nt++)
        #pragma unroll
        for (int e = 0; e < 4; e++) oc[nt][e] = 0.f;
    float m2[2] = {-INFINITY, -INFINITY};
    float l2[2] = {0.f, 0.f};

    uint32_t brow = (((uint32_t)((lane >> 4) * 8 + (lane & 7))) * TPAD +
                     ((lane >> 3) & 1) * 8) * 2;
    uint32_t vrow = (((uint32_t)(((lane >> 3) & 1) * 8 + (lane & 7))) * TPAD +
                     ((lane >> 4) * 8)) * 2;

    for (int ic = 0; ic < nchunks; ic++) {
        int kc = kstart + ic * 64;
        uint32_t kv = sb + KV_BASE + (uint32_t)(ic & 1) * 3 * TILE_BYTES;

        if (ic > 0) {
            asm volatile("cp.async.wait_group 0;");
            __syncthreads();
        }
        if (ic + 1 < nchunks) {
            int kn = kc + 64;
            size_t kb = ((size_t)b * S_LEN + kn) * NQKV + D_MODEL + h * DKH;
            size_t vb = ((size_t)b * S_LEN + kn) * NQKV + 2 * D_MODEL + h * DKH;
            uint32_t kvn = sb + KV_BASE + (uint32_t)((ic + 1) & 1) * 3 * TILE_BYTES;
            ldtile_async(kvn + 0 * TILE_BYTES, qkvh + kb, tid);
            ldtile_async(kvn + 1 * TILE_BYTES, qkvl + kb, tid);
            ldtile_async(kvn + 2 * TILE_BYTES, qkvh + vb, tid);
            asm volatile("cp.async.commit_group;");
        }

        // ---- S = Q K^T (3-term) ----
        float sc[8][4];
        #pragma unroll
        for (int nt = 0; nt < 8; nt++)
            #pragma unroll
            for (int e = 0; e < 4; e++) sc[nt][e] = 0.f;

        #pragma unroll
        for (int s = 0; s < 4; s++) {
            uint32_t kbf[8][2];
            #pragma unroll
            for (int np = 0; np < 4; np++)
                ldmx4(kbf[2*np][0], kbf[2*np][1], kbf[2*np+1][0], kbf[2*np+1][1],
                      kv + 0 * TILE_BYTES + brow + (uint32_t)(np * 16 * TPAD) * 2 + s * 32);
            #pragma unroll
            for (int nt = 0; nt < 8; nt++) hmma(sc[nt], qh4[s], kbf[nt][0], kbf[nt][1]);
            #pragma unroll
            for (int nt = 0; nt < 8; nt++) hmma(sc[nt], ql4[s], kbf[nt][0], kbf[nt][1]);
            #pragma unroll
            for (int np = 0; np < 4; np++)
                ldmx4(kbf[2*np][0], kbf[2*np][1], kbf[2*np+1][0], kbf[2*np+1][1],
                      kv + 1 * TILE_BYTES + brow + (uint32_t)(np * 16 * TPAD) * 2 + s * 32);
            #pragma unroll
            for (int nt = 0; nt < 8; nt++) hmma(sc[nt], qh4[s], kbf[nt][0], kbf[nt][1]);
        }

        // ---- scale + ALiBi + window mask ----
        #pragma unroll
        for (int nt = 0; nt < 8; nt++) {
            #pragma unroll
            for (int e = 0; e < 4; e++) {
                int row = q0 + m0 + g + (e >= 2 ? 8 : 0);
                int col = kc + nt * 8 + 2 * t + (e & 1);
                int d = row - col;
                float sv = sc[nt][e] * 0.125f + slope * (float)d;
                if (d > HALF_WIN || d < -HALF_WIN) sv = -INFINITY;
                sc[nt][e] = sv;
            }
        }

        // ---- in-warp softmax ----
        #pragma unroll
        for (int half = 0; half < 2; half++) {
            float mx = -INFINITY;
            #pragma unroll
            for (int nt = 0; nt < 8; nt++)
                mx = fmaxf(mx, fmaxf(sc[nt][2*half], sc[nt][2*half+1]));
            mx = fmaxf(mx, __shfl_xor_sync(0xffffffffu, mx, 1));
            mx = fmaxf(mx, __shfl_xor_sync(0xffffffffu, mx, 2));
            float mnew = fmaxf(m2[half], mx);

            float alpha, lsum = 0.f;
            if (mnew == -INFINITY) {
                alpha = 1.f;
                #pragma unroll
                for (int nt = 0; nt < 8; nt++) {
                    sc[nt][2*half] = 0.f; sc[nt][2*half+1] = 0.f;
                }
            } else {
                alpha = __expf(m2[half] - mnew);
                #pragma unroll
                for (int nt = 0; nt < 8; nt++) {
                    float p0 = __expf(sc[nt][2*half]   - mnew);
                    float p1 = __expf(sc[nt][2*half+1] - mnew);
                    sc[nt][2*half] = p0; sc[nt][2*half+1] = p1;
                    lsum += p0 + p1;
                }
            }
            lsum += __shfl_xor_sync(0xffffffffu, lsum, 1);
            lsum += __shfl_xor_sync(0xffffffffu, lsum, 2);
            l2[half] = l2[half] * alpha + lsum;
            m2[half] = mnew;
            #pragma unroll
            for (int nt = 0; nt < 8; nt++) {
                oc[nt][2*half]   *= alpha;
                oc[nt][2*half+1] *= alpha;
            }
        }

        // ---- O += P V (1-term: ph * vh) ----
        #pragma unroll
        for (int kk = 0; kk < 4; kk++) {
            uint32_t ah[4];
            ah[0] = pkh(sc[2*kk][0],   sc[2*kk][1]);
            ah[1] = pkh(sc[2*kk][2],   sc[2*kk][3]);
            ah[2] = pkh(sc[2*kk+1][0], sc[2*kk+1][1]);
            ah[3] = pkh(sc[2*kk+1][2], sc[2*kk+1][3]);
            uint32_t vbf[8][2];
            #pragma unroll
            for (int np = 0; np < 4; np++)
                ldmx4t(vbf[2*np][0], vbf[2*np][1], vbf[2*np+1][0], vbf[2*np+1][1],
                       kv + 2 * TILE_BYTES + vrow + (uint32_t)(kk * 16 * TPAD + np * 16) * 2);
            #pragma unroll
            for (int nt = 0; nt < 8; nt++) hmma(oc[nt], ah, vbf[nt][0], vbf[nt][1]);
        }
    }

    // epilogue: normalize + plain fp16 write into aoa
    float inv0 = 1.f / l2[0], inv1 = 1.f / l2[1];
    int row0 = q0 + m0 + g;
    size_t r0b = ((size_t)b * S_LEN + row0) * D_MODEL + h * DKH;
    size_t r1b = ((size_t)b * S_LEN + row0 + 8) * D_MODEL + h * DKH;
    #pragma unroll
    for (int nt = 0; nt < 8; nt++) {
        int col = nt * 8 + 2 * t;
        #pragma unroll
        for (int half = 0; half < 2; half++) {
            float v0 = oc[nt][2*half]   * (half ? inv1 : inv0);
            float v1 = oc[nt][2*half+1] * (half ? inv1 : inv0);
            size_t base = (half ? r1b : r0b) + col;
            *(__half2*)&oa[base] = __halves2half2(__float2half(v0), __float2half(v1));
        }
    }
}

// ---------------------------------------------------------------------------
extern "C" void kernel_launch(void* const* d_in, const int* in_sizes, int n_in,
                              void* d_out, int out_size)
{
    const float* x      = (const float*)d_in[0];
    const float* Wq     = (const float*)d_in[1];
    const float* Wk     = (const float*)d_in[2];
    const float* Wv     = (const float*)d_in[3];
    const float* Wo     = (const float*)d_in[4];
    const float* slopes = (const float*)d_in[5];
    float* out = (float*)d_out;

    __half *qh, *ql, *xa, *aoa, *wqkv, *wo;
    cudaGetSymbolAddress((void**)&qh,   g_qh);
    cudaGetSymbolAddress((void**)&ql,   g_ql);
    cudaGetSymbolAddress((void**)&xa,   g_xa);
    cudaGetSymbolAddress((void**)&aoa,  g_aoa);
    cudaGetSymbolAddress((void**)&wqkv, g_wqkv);
    cudaGetSymbolAddress((void**)&wo,   g_wo);

    cudaFuncSetAttribute((const void*)gemm_mma<true, D_MODEL>,
                         cudaFuncAttributeMaxDynamicSharedMemorySize, SMEM_GEMM);
    cudaFuncSetAttribute((const void*)gemm_mma<true, D_MODEL>,
                         cudaFuncAttributePreferredSharedMemoryCarveout, 100);
    cudaFuncSetAttribute((const void*)gemm_mma<false, D_MODEL>,
                         cudaFuncAttributeMaxDynamicSharedMemorySize, SMEM_GEMM);
    cudaFuncSetAttribute((const void*)gemm_mma<false, D_MODEL>,
                         cudaFuncAttributePreferredSharedMemoryCarveout, 100);
    cudaFuncSetAttribute(attn_tc, cudaFuncAttributeMaxDynamicSharedMemorySize,
                         SMEM_ATTN);
    cudaFuncSetAttribute(attn_tc, cudaFuncAttributePreferredSharedMemoryCarveout,
                         100);

    conv_all<<<dim3(MROWS, 2), 256>>>(x, Wq, Wk, Wv, Wo, xa, wqkv, wo);

    // QKV projection (plain fp16, K=1024) -> fp16 hi/lo pair arrays
    gemm_mma<true, D_MODEL><<<dim3(NQKV / GBN, MROWS / GBM), 256, SMEM_GEMM>>>(
        xa, wqkv, nullptr, qh, ql, NQKV);

    // tensor-core attention -> plain fp16 aoa
    attn_tc<<<dim3(S_LEN / BQ, NHEADS, BATCH), 128, SMEM_ATTN>>>(
        qh, ql, slopes, aoa);

    // output projection (plain fp16, K=1024) -> fp32 result
    gemm_mma<false, D_MODEL><<<dim3(D_MODEL / GBN, MROWS / GBM), 256, SMEM_GEMM>>>(
        aoa, wo, out, nullptr, nullptr, D_MODEL);
}